// round 5
// baseline (speedup 1.0000x reference)
#include <cuda_runtime.h>
#include <math.h>

#define BB 4
#define CC 32
#define NHEAD 4
#define HDIM 8
#define NN 32768
#define PP 64

// ---------------- scratch (static device memory; no allocations) ----------------
static __device__ float g_xt  [BB*NN*CC];   // tokens + pos  [b][n][c]
static __device__ float g_q   [BB*CC*NN];   // [b*32+c][n],  c = h*8+d
static __device__ float g_k   [BB*CC*NN];
static __device__ float g_vca [BB*CC*NN];
static __device__ float g_vsa [BB*CC*NN];
static __device__ float g_part[64*256*PP];  // split-K partials for EF projections
static __device__ float g_kproj[BB*CC*PP];
static __device__ float g_vproj[BB*CC*PP];
static __device__ float g_npart[8*16*80];   // gram/norm partials
static __device__ float g_qinv[BB*CC];
static __device__ float g_attnca[BB*NHEAD*HDIM*HDIM];
static __device__ float g_xsa [BB*CC*NN];   // [b][h][d][n]
static __device__ float g_xca [BB*CC*NN];
static __device__ float g_skip[BB*CC*NN];   // attn_skip [B][C][32][32][32]
static __device__ float g_y1  [BB*CC*NN];
static __device__ float g_y2  [BB*CC*NN];

// ---------------- packed f32x2 helpers ----------------
typedef unsigned long long u64t;
__device__ __forceinline__ u64t pk2(float lo, float hi) {
    u64t r; asm("mov.b64 %0, {%1, %2};" : "=l"(r) : "f"(lo), "f"(hi)); return r;
}
__device__ __forceinline__ void upk2(u64t v, float& lo, float& hi) {
    asm("mov.b64 {%0, %1}, %2;" : "=f"(lo), "=f"(hi) : "l"(v));
}
__device__ __forceinline__ u64t ffma2(u64t a, u64t b, u64t c) {
    u64t d; asm("fma.rn.f32x2 %0, %1, %2, %3;" : "=l"(d) : "l"(a), "l"(b), "l"(c)); return d;
}

// ---------------- K1: transpose+pos, layernorm, QKVV GEMM ----------------
__global__ __launch_bounds__(256) void k1_tok_ln_qkvv(
    const float* __restrict__ x, const float* __restrict__ pos,
    const float* __restrict__ lng, const float* __restrict__ lnb,
    const float* __restrict__ Wq)
{
    __shared__ float xts[32][33];
    __shared__ float Ws[32][128];
    int b  = blockIdx.x >> 10;
    int n0 = (blockIdx.x & 1023) << 5;
    int t  = threadIdx.x;

    for (int i = t; i < 32*128; i += 256) Ws[i >> 7][i & 127] = Wq[i];
    for (int i = t; i < 1024; i += 256) {
        int j = i & 31, c = i >> 5;
        xts[j][c] = x[(b*CC + c)*NN + n0 + j];
    }
    __syncthreads();
    for (int i = t; i < 1024; i += 256) {
        int c = i & 31, j = i >> 5;
        float v = xts[j][c] + pos[(n0 + j)*CC + c];
        xts[j][c] = v;
        g_xt[(b*NN + n0 + j)*CC + c] = v;
    }
    __syncthreads();
    int w = t >> 5, lane = t & 31;
    for (int jj = 0; jj < 4; jj++) {
        int j = w*4 + jj;
        float v = xts[j][lane];
        float s = v, ss = v*v;
        #pragma unroll
        for (int o = 16; o > 0; o >>= 1) {
            s  += __shfl_xor_sync(0xffffffffu, s, o);
            ss += __shfl_xor_sync(0xffffffffu, ss, o);
        }
        float mu  = s * (1.0f/32.0f);
        float var = ss * (1.0f/32.0f) - mu*mu;
        float r   = rsqrtf(var + 1e-5f);
        xts[j][lane] = (v - mu) * r * lng[lane] + lnb[lane];
    }
    __syncthreads();
    float acc[16];
    #pragma unroll
    for (int i = 0; i < 16; i++) acc[i] = 0.f;
    int c0 = w * 16;
    #pragma unroll
    for (int kk = 0; kk < 32; kk++) {
        float xv = xts[lane][kk];
        #pragma unroll
        for (int i = 0; i < 16; i++) acc[i] += xv * Ws[kk][c0 + i];
    }
    #pragma unroll
    for (int i = 0; i < 16; i++) {
        int col   = c0 + i;
        int which = col >> 5;
        int ch    = col & 31;
        float* dst = (which == 0) ? g_q : (which == 1) ? g_k :
                     (which == 2) ? g_vca : g_vsa;
        dst[(b*CC + ch)*NN + n0 + lane] = acc[i];
    }
}

// ---------------- K2: EF projections (split-K GEMM, partial) ----------------
__global__ __launch_bounds__(128) void k2_proj_partial(const float* __restrict__ EFw)
{
    __shared__ __align__(16) float Ks[64][68];
    __shared__ __align__(16) float Es[64][68];
    int chunk = blockIdx.x;
    int rg    = blockIdx.y;
    int t     = threadIdx.x;
    const float* src = (rg < 2) ? g_k : g_vsa;
    int r0  = (rg & 1) * 64;
    int nb0 = chunk * 512;

    float acc[4][8];
    #pragma unroll
    for (int i = 0; i < 4; i++)
        #pragma unroll
        for (int j = 0; j < 8; j++) acc[i][j] = 0.f;

    int pb = (t & 7) * 8;
    int ro = (t >> 3) * 4;
    for (int st = 0; st < 8; st++) {
        int nb = nb0 + st*64;
        __syncthreads();
        for (int i = t; i < 64*64; i += 128) {
            int nn = i & 63, rr = i >> 6;
            Ks[rr][nn] = src[(r0 + rr)*NN + nb + nn];
            Es[rr][nn] = EFw[rr*NN + nb + nn];
        }
        __syncthreads();
        #pragma unroll 4
        for (int nn = 0; nn < 64; nn += 4) {
            float4 rv[4];
            #pragma unroll
            for (int i = 0; i < 4; i++)
                rv[i] = *reinterpret_cast<const float4*>(&Ks[ro + i][nn]);
            #pragma unroll
            for (int j = 0; j < 8; j++) {
                float4 e = *reinterpret_cast<const float4*>(&Es[pb + j][nn]);
                #pragma unroll
                for (int i = 0; i < 4; i++) {
                    acc[i][j] += rv[i].x*e.x + rv[i].y*e.y
                               + rv[i].z*e.z + rv[i].w*e.w;
                }
            }
        }
    }
    #pragma unroll
    for (int i = 0; i < 4; i++)
        #pragma unroll
        for (int j = 0; j < 8; j++)
            g_part[(chunk*256 + rg*64 + ro + i)*PP + pb + j] = acc[i][j];
}

__global__ __launch_bounds__(256) void k2_proj_reduce(const float* __restrict__ EFb)
{
    int idx = blockIdx.x * 256 + threadIdx.x;
    int row = idx >> 6, p = idx & 63;
    float s = 0.f;
    for (int c = 0; c < 64; c++) s += g_part[(c*256 + row)*PP + p];
    s += EFb[p];
    if (row < 128) g_kproj[row*PP + p] = s;
    else           g_vproj[(row - 128)*PP + p] = s;
}

// ---------------- K3a: gram matrix + L2 norms (partial) ----------------
__global__ __launch_bounds__(256) void k3a_gram_partial()
{
    int split = blockIdx.x;
    int bh    = blockIdx.y;
    int t     = threadIdx.x;
    const float* qb = g_q + bh*8*NN;
    const float* kb = g_k + bh*8*NN;

    float v[80];
    #pragma unroll
    for (int i = 0; i < 80; i++) v[i] = 0.f;

    int nend = split*4096 + 4096;
    for (int n = split*4096 + t; n < nend; n += 256) {
        float qv[8], kv[8];
        #pragma unroll
        for (int d = 0; d < 8; d++) { qv[d] = qb[d*NN + n]; kv[d] = kb[d*NN + n]; }
        #pragma unroll
        for (int d = 0; d < 8; d++) {
            v[64 + d] += qv[d]*qv[d];
            v[72 + d] += kv[d]*kv[d];
            #pragma unroll
            for (int e = 0; e < 8; e++) v[d*8 + e] += qv[d]*kv[e];
        }
    }
    __shared__ float wsum[8][80];
    int w = t >> 5, lane = t & 31;
    #pragma unroll
    for (int i = 0; i < 80; i++) {
        float s = v[i];
        #pragma unroll
        for (int o = 16; o > 0; o >>= 1) s += __shfl_xor_sync(0xffffffffu, s, o);
        if (lane == 0) wsum[w][i] = s;
    }
    __syncthreads();
    if (t < 80) {
        float s = 0.f;
        #pragma unroll
        for (int ww = 0; ww < 8; ww++) s += wsum[ww][t];
        g_npart[(split*16 + bh)*80 + t] = s;
    }
}

// ---------------- K3a2: finalize norms + channel-attention softmax ----------------
__global__ __launch_bounds__(128) void k3a_finalize(const float* __restrict__ temp1)
{
    int bh = blockIdx.x;
    int t  = threadIdx.x;
    __shared__ float tot[80];
    __shared__ float qi[8], ki[8];
    if (t < 80) {
        float s = 0.f;
        #pragma unroll
        for (int sp = 0; sp < 8; sp++) s += g_npart[(sp*16 + bh)*80 + t];
        tot[t] = s;
    }
    __syncthreads();
    if (t < 8) {
        float qn = sqrtf(tot[64 + t]);
        float kn = sqrtf(tot[72 + t]);
        qi[t] = 1.0f / fmaxf(qn, 1e-12f);
        ki[t] = 1.0f / fmaxf(kn, 1e-12f);
        g_qinv[bh*8 + t] = qi[t];
    }
    __syncthreads();
    if (t < 8) {
        int h = bh & 3;
        float t1 = temp1[h];
        float sc[8];
        float m = -1e30f;
        #pragma unroll
        for (int e = 0; e < 8; e++) {
            sc[e] = tot[t*8 + e] * qi[t] * ki[e] * t1;
            m = fmaxf(m, sc[e]);
        }
        float sum = 0.f;
        #pragma unroll
        for (int e = 0; e < 8; e++) { sc[e] = __expf(sc[e] - m); sum += sc[e]; }
        float inv = 1.0f / sum;
        #pragma unroll
        for (int e = 0; e < 8; e++) g_attnca[bh*64 + t*8 + e] = sc[e]*inv;
    }
}

// ---------------- K3b: spatial attention per token + channel-attn apply ----------------
__global__ __launch_bounds__(128) void k3b_attn(const float* __restrict__ temp2)
{
    int bh = blockIdx.y;
    int n  = blockIdx.x * 128 + threadIdx.x;
    int h  = bh & 3;
    int t  = threadIdx.x;
    __shared__ float kq[8][64], vp[8][64], A[8][8];
    float t2 = temp2[h];
    for (int i = t; i < 512; i += 128) {
        int d = i >> 6, p = i & 63;
        kq[d][p] = g_qinv[bh*8 + d] * g_kproj[(bh*8 + d)*PP + p] * t2;
        vp[d][p] = g_vproj[(bh*8 + d)*PP + p];
    }
    if (t < 64) A[t >> 3][t & 7] = g_attnca[bh*64 + t];
    __syncthreads();

    int base = bh*8*NN + n;
    float qv[8];
    #pragma unroll
    for (int d = 0; d < 8; d++) qv[d] = g_q[base + d*NN];

    float s[64];
    #pragma unroll
    for (int p = 0; p < 64; p++) s[p] = qv[0]*kq[0][p];
    #pragma unroll
    for (int d = 1; d < 8; d++)
        #pragma unroll
        for (int p = 0; p < 64; p++) s[p] += qv[d]*kq[d][p];

    float m = s[0];
    #pragma unroll
    for (int p = 1; p < 64; p++) m = fmaxf(m, s[p]);
    float sum = 0.f;
    #pragma unroll
    for (int p = 0; p < 64; p++) { s[p] = __expf(s[p] - m); sum += s[p]; }
    float inv = 1.0f / sum;

    #pragma unroll
    for (int d = 0; d < 8; d++) {
        float o = 0.f;
        #pragma unroll
        for (int p = 0; p < 64; p++) o += s[p]*vp[d][p];
        g_xsa[base + d*NN] = o * inv;
    }
    float vv[8];
    #pragma unroll
    for (int e = 0; e < 8; e++) vv[e] = g_vca[base + e*NN];
    #pragma unroll
    for (int d = 0; d < 8; d++) {
        float xc = 0.f;
        #pragma unroll
        for (int e = 0; e < 8; e++) xc += A[d][e]*vv[e];
        g_xca[base + d*NN] = xc;
    }
}

// ---------------- K4: scramble-gather, out1/out2 linears, gamma residual ----------------
__global__ __launch_bounds__(128) void k4_combine(
    const float* __restrict__ o1w, const float* __restrict__ o1b,
    const float* __restrict__ o2w, const float* __restrict__ o2b,
    const float* __restrict__ gamma)
{
    __shared__ float sa[32][33], ca[32][33], xtl[32][33];
    __shared__ float w1[16][32], w2[16][32], b1[16], b2[16], gm[32];
    int b  = blockIdx.x >> 10;
    int t0 = (blockIdx.x & 1023) << 5;
    int t  = threadIdx.x;
    int dd   = t0 >> 12;
    int hh   = (t0 >> 10) & 3;
    int nsrc = (t0 & 1023) << 5;

    const float* sap = g_xsa + ((b*NHEAD + hh)*HDIM + dd)*NN + nsrc;
    for (int i = t; i < 1024; i += 128) sa[i >> 5][i & 31] = sap[i];
    for (int i = t; i < 1024; i += 128) {
        int c = i >> 5, ii = i & 31;
        ca[ii][c] = g_xca[(b*CC + c)*NN + t0 + ii];
    }
    for (int i = t; i < 1024; i += 128) {
        int ii = i >> 5, c = i & 31;
        xtl[ii][c] = g_xt[(b*NN + t0 + ii)*CC + c];
    }
    for (int i = t; i < 512; i += 128) {
        w1[i >> 5][i & 31] = o1w[i];
        w2[i >> 5][i & 31] = o2w[i];
    }
    if (t < 16) { b1[t] = o1b[t]; b2[t] = o2b[t]; }
    if (t < 32) gm[t] = gamma[t];
    __syncthreads();

    int ii = t & 31;
    int cg = t >> 5;
    #pragma unroll
    for (int cc = 0; cc < 8; cc++) {
        int c = cg*8 + cc;
        float val;
        if (c < 16) {
            float s = b1[c];
            #pragma unroll
            for (int k = 0; k < 32; k++) s += sa[ii][k]*w1[c][k];
            val = s;
        } else {
            int j = c - 16;
            float s = b2[j];
            #pragma unroll
            for (int k = 0; k < 32; k++) s += ca[ii][k]*w2[j][k];
            val = s;
        }
        float r = xtl[ii][c] + gm[c]*val;
        g_skip[(b*CC + c)*NN + t0 + ii] = r;
    }
}

// ---------------- conv 3x3x3 + BN (+residual) + LeakyReLU  (f32x2 FFMA2 version) ----------------
// Block: 128 threads. Thread tile: 8 co x 8 x (accs as 8x4 f32x2 over x-pairs).
// Block tile: 32co x 8y x 32x at one z. Grid: (4 ygroups, 32 z, 4 batch) = 512 blocks.
// ci processed in 8 passes of 4; weights pre-broadcast (w,w) in smem -> LDS.64 broadcast.
#define CIP 4
template<int MODE>
__global__ __launch_bounds__(128) void conv3_bn(
    const float* __restrict__ w,  const float* __restrict__ cb,
    const float* __restrict__ bg, const float* __restrict__ bb,
    const float* __restrict__ bm, const float* __restrict__ bv)
{
    __shared__ __align__(16) float xs[CIP][3][10][36];      // [ci][zz][yy][xx] 17.3KB
    __shared__ __align__(16) u64t  wbs[CIP*27*32];          // [ci][kz][ky][kx][co] (w,w) 27.6KB
    __shared__ float scs[32], bss[32];
    const float* in  = (MODE == 1) ? g_skip : g_y1;
    float*       out = (MODE == 1) ? g_y1   : g_y2;
    const float* res = g_skip;

    int y0 = blockIdx.x * 8;
    int z  = blockIdx.y;
    int b  = blockIdx.z;
    int t  = threadIdx.x;
    if (t < 32) {
        float a = bg[t]*rsqrtf(bv[t] + 1e-5f);
        scs[t] = a;
        bss[t] = (cb[t] - bm[t])*a + bb[t];
    }
    int cg  = t & 3;             // co group: co0 = cg*8
    int xg  = (t >> 2) & 3;      // x group:  xb = xg*8
    int ty  = t >> 4;            // 0..7
    int co0 = cg * 8;
    int xb  = xg * 8;

    u64t acc[8][4];
    #pragma unroll
    for (int c = 0; c < 8; c++)
        #pragma unroll
        for (int j = 0; j < 4; j++) acc[c][j] = 0ull;

    for (int pass = 0; pass < 8; pass++) {
        int cio = pass * CIP;
        __syncthreads();
        // ---- load input tile (coalesced along x) ----
        for (int fl = t; fl < CIP*3*10*34; fl += 128) {
            int xx = fl % 34; int r2 = fl / 34;
            int yy = r2 % 10; r2 /= 10;
            int zz = r2 % 3;  int ci = r2 / 3;
            int zg = z + zz - 1, ygl = y0 + yy - 1, xgc = xx - 1;
            float v = 0.f;
            if ((unsigned)zg < 32u && (unsigned)ygl < 32u && (unsigned)xgc < 32u)
                v = in[(((b*32 + cio + ci)*32 + zg)*32 + ygl)*32 + xgc];
            xs[ci][zz][yy][xx] = v;
        }
        // ---- load weights for this pass, pre-broadcast (w,w); coalesced along taps ----
        for (int fl = t; fl < 32*CIP*27; fl += 128) {
            int tap = fl % 27; int r2 = fl / 27;
            int ci  = r2 % CIP;
            int co  = r2 / CIP;
            float v = w[(co*32 + cio + ci)*27 + tap];
            wbs[(ci*27 + tap)*32 + co] = pk2(v, v);
        }
        __syncthreads();
        // ---- compute ----
        #pragma unroll
        for (int ci = 0; ci < CIP; ci++) {
            #pragma unroll
            for (int kz = 0; kz < 3; kz++) {
                #pragma unroll
                for (int ky = 0; ky < 3; ky++) {
                    const float2* xrow = reinterpret_cast<const float2*>(&xs[ci][kz][ty + ky][xb]);
                    float2 e0 = xrow[0], e1 = xrow[1], e2 = xrow[2], e3 = xrow[3], e4 = xrow[4];
                    u64t xe0 = pk2(e0.x, e0.y), xe1 = pk2(e1.x, e1.y), xe2 = pk2(e2.x, e2.y),
                         xe3 = pk2(e3.x, e3.y), xe4 = pk2(e4.x, e4.y);
                    u64t xo0 = pk2(e0.y, e1.x), xo1 = pk2(e1.y, e2.x),
                         xo2 = pk2(e2.y, e3.x), xo3 = pk2(e3.y, e4.x);
                    const u64t* wrow = &wbs[(ci*27 + (kz*3 + ky)*3)*32 + co0];
                    #pragma unroll
                    for (int c = 0; c < 8; c++) {
                        u64t w0 = wrow[c];
                        u64t w1 = wrow[32 + c];
                        u64t w2 = wrow[64 + c];
                        acc[c][0] = ffma2(w0, xe0, acc[c][0]);
                        acc[c][1] = ffma2(w0, xe1, acc[c][1]);
                        acc[c][2] = ffma2(w0, xe2, acc[c][2]);
                        acc[c][3] = ffma2(w0, xe3, acc[c][3]);
                        acc[c][0] = ffma2(w1, xo0, acc[c][0]);
                        acc[c][1] = ffma2(w1, xo1, acc[c][1]);
                        acc[c][2] = ffma2(w1, xo2, acc[c][2]);
                        acc[c][3] = ffma2(w1, xo3, acc[c][3]);
                        acc[c][0] = ffma2(w2, xe1, acc[c][0]);
                        acc[c][1] = ffma2(w2, xe2, acc[c][1]);
                        acc[c][2] = ffma2(w2, xe3, acc[c][2]);
                        acc[c][3] = ffma2(w2, xe4, acc[c][3]);
                    }
                }
            }
        }
    }
    // ---- epilogue: BN (+res) + LeakyReLU, two float4 stores per co ----
    #pragma unroll
    for (int c = 0; c < 8; c++) {
        int co = co0 + c;
        int base = (((b*32 + co)*32 + z)*32 + (y0 + ty))*32 + xb;
        float a = scs[co], bo = bss[co];
        float f[8];
        #pragma unroll
        for (int j = 0; j < 4; j++) upk2(acc[c][j], f[2*j], f[2*j + 1]);
        #pragma unroll
        for (int u = 0; u < 8; u++) {
            float v = f[u]*a + bo;
            if (MODE == 1) {
                v = (v > 0.f) ? v : 0.01f*v;
            } else {
                v += res[base + u];
                v = (v > 0.f) ? v : 0.01f*v;
            }
            f[u] = v;
        }
        *reinterpret_cast<float4*>(&out[base])     = make_float4(f[0], f[1], f[2], f[3]);
        *reinterpret_cast<float4*>(&out[base + 4]) = make_float4(f[4], f[5], f[6], f[7]);
    }
}

// ---------------- final: 1x1 conv residual ----------------
__global__ __launch_bounds__(256) void k_final(
    const float* __restrict__ wp, const float* __restrict__ bp,
    float* __restrict__ outp)
{
    __shared__ float ys[32][64];
    __shared__ float wsm[32][32];
    __shared__ float bsh[32];
    int b  = blockIdx.x >> 9;
    int n0 = (blockIdx.x & 511) << 6;
    int t  = threadIdx.x;
    for (int i = t; i < 2048; i += 256) {
        int ci = i >> 6, nn = i & 63;
        ys[ci][nn] = g_y2[(b*32 + ci)*NN + n0 + nn];
    }
    for (int i = t; i < 1024; i += 256) wsm[i >> 5][i & 31] = wp[i];
    if (t < 32) bsh[t] = bp[t];
    __syncthreads();
    int nn = t & 63;
    int cg = t >> 6;
    #pragma unroll
    for (int cc = 0; cc < 8; cc++) {
        int co = cg*8 + cc;
        float s = bsh[co];
        #pragma unroll
        for (int ci = 0; ci < 32; ci++) s += wsm[co][ci]*ys[ci][nn];
        int idx = (b*32 + co)*NN + n0 + nn;
        outp[idx] = g_skip[idx] + s;
    }
}

// ---------------- launch ----------------
extern "C" void kernel_launch(void* const* d_in, const int* in_sizes, int n_in,
                              void* d_out, int out_size)
{
    const float* x    = (const float*)d_in[0];
    const float* pos  = (const float*)d_in[1];
    const float* lng  = (const float*)d_in[2];
    const float* lnb  = (const float*)d_in[3];
    const float* gam  = (const float*)d_in[4];
    const float* Wq   = (const float*)d_in[5];
    const float* EFw  = (const float*)d_in[6];
    const float* EFb  = (const float*)d_in[7];
    const float* t1   = (const float*)d_in[8];
    const float* t2   = (const float*)d_in[9];
    const float* o1w  = (const float*)d_in[10];
    const float* o1b  = (const float*)d_in[11];
    const float* o2w  = (const float*)d_in[12];
    const float* o2b  = (const float*)d_in[13];
    const float* c1w  = (const float*)d_in[14];
    const float* c1b  = (const float*)d_in[15];
    const float* b1g  = (const float*)d_in[16];
    const float* b1b  = (const float*)d_in[17];
    const float* b1m  = (const float*)d_in[18];
    const float* b1v  = (const float*)d_in[19];
    const float* c2w  = (const float*)d_in[20];
    const float* c2b  = (const float*)d_in[21];
    const float* b2g  = (const float*)d_in[22];
    const float* b2b  = (const float*)d_in[23];
    const float* b2m  = (const float*)d_in[24];
    const float* b2v  = (const float*)d_in[25];
    const float* cpw  = (const float*)d_in[26];
    const float* cpb  = (const float*)d_in[27];
    float* outp = (float*)d_out;

    k1_tok_ln_qkvv<<<4096, 256>>>(x, pos, lng, lnb, Wq);
    k2_proj_partial<<<dim3(64, 4), 128>>>(EFw);
    k2_proj_reduce<<<64, 256>>>(EFb);
    k3a_gram_partial<<<dim3(8, 16), 256>>>();
    k3a_finalize<<<16, 128>>>(t1);
    k3b_attn<<<dim3(256, 16), 128>>>(t2);
    k4_combine<<<4096, 128>>>(o1w, o1b, o2w, o2b, gam);
    conv3_bn<1><<<dim3(4, 32, 4), 128>>>(c1w, c1b, b1g, b1b, b1m, b1v);
    conv3_bn<2><<<dim3(4, 32, 4), 128>>>(c2w, c2b, b2g, b2b, b2m, b2v);
    k_final<<<2048, 256>>>(cpw, cpb, outp);
}

// round 8
// speedup vs baseline: 1.1889x; 1.1889x over previous
#include <cuda_runtime.h>
#include <math.h>

#define BB 4
#define CC 32
#define NHEAD 4
#define HDIM 8
#define NN 32768
#define PP 64

// ---------------- scratch (static device memory; no allocations) ----------------
static __device__ float g_xt  [BB*NN*CC];   // tokens + pos  [b][n][c]
static __device__ float g_q   [BB*CC*NN];   // [b*32+c][n],  c = h*8+d
static __device__ float g_k   [BB*CC*NN];
static __device__ float g_vca [BB*CC*NN];
static __device__ float g_vsa [BB*CC*NN];
static __device__ float g_part[64*256*PP];  // split-K partials for EF projections
static __device__ float g_kproj[BB*CC*PP];
static __device__ float g_vproj[BB*CC*PP];
static __device__ float g_npart[8*16*80];   // gram/norm partials
static __device__ float g_qinv[BB*CC];
static __device__ float g_attnca[BB*NHEAD*HDIM*HDIM];
static __device__ float g_xsa [BB*CC*NN];   // [b][h][d][n]
static __device__ float g_xca [BB*CC*NN];
static __device__ float g_skip[BB*CC*NN];   // attn_skip [B][C][32][32][32]
static __device__ float g_y1  [BB*CC*NN];
static __device__ float g_y2  [BB*CC*NN];

// ---------------- K1: transpose+pos, layernorm, QKVV GEMM ----------------
__global__ __launch_bounds__(256) void k1_tok_ln_qkvv(
    const float* __restrict__ x, const float* __restrict__ pos,
    const float* __restrict__ lng, const float* __restrict__ lnb,
    const float* __restrict__ Wq)
{
    __shared__ float xts[32][33];
    __shared__ float Ws[32][128];
    int b  = blockIdx.x >> 10;
    int n0 = (blockIdx.x & 1023) << 5;
    int t  = threadIdx.x;

    for (int i = t; i < 32*128; i += 256) Ws[i >> 7][i & 127] = Wq[i];
    for (int i = t; i < 1024; i += 256) {
        int j = i & 31, c = i >> 5;
        xts[j][c] = x[(b*CC + c)*NN + n0 + j];
    }
    __syncthreads();
    for (int i = t; i < 1024; i += 256) {
        int c = i & 31, j = i >> 5;
        float v = xts[j][c] + pos[(n0 + j)*CC + c];
        xts[j][c] = v;
        g_xt[(b*NN + n0 + j)*CC + c] = v;
    }
    __syncthreads();
    int w = t >> 5, lane = t & 31;
    for (int jj = 0; jj < 4; jj++) {
        int j = w*4 + jj;
        float v = xts[j][lane];
        float s = v, ss = v*v;
        #pragma unroll
        for (int o = 16; o > 0; o >>= 1) {
            s  += __shfl_xor_sync(0xffffffffu, s, o);
            ss += __shfl_xor_sync(0xffffffffu, ss, o);
        }
        float mu  = s * (1.0f/32.0f);
        float var = ss * (1.0f/32.0f) - mu*mu;
        float r   = rsqrtf(var + 1e-5f);
        xts[j][lane] = (v - mu) * r * lng[lane] + lnb[lane];
    }
    __syncthreads();
    float acc[16];
    #pragma unroll
    for (int i = 0; i < 16; i++) acc[i] = 0.f;
    int c0 = w * 16;
    #pragma unroll
    for (int kk = 0; kk < 32; kk++) {
        float xv = xts[lane][kk];
        #pragma unroll
        for (int i = 0; i < 16; i++) acc[i] += xv * Ws[kk][c0 + i];
    }
    #pragma unroll
    for (int i = 0; i < 16; i++) {
        int col   = c0 + i;
        int which = col >> 5;
        int ch    = col & 31;
        float* dst = (which == 0) ? g_q : (which == 1) ? g_k :
                     (which == 2) ? g_vca : g_vsa;
        dst[(b*CC + ch)*NN + n0 + lane] = acc[i];
    }
}

// ---------------- K2: EF projections (split-K GEMM, partial) ----------------
__global__ __launch_bounds__(128) void k2_proj_partial(const float* __restrict__ EFw)
{
    __shared__ __align__(16) float Ks[64][68];
    __shared__ __align__(16) float Es[64][68];
    int chunk = blockIdx.x;
    int rg    = blockIdx.y;
    int t     = threadIdx.x;
    const float* src = (rg < 2) ? g_k : g_vsa;
    int r0  = (rg & 1) * 64;
    int nb0 = chunk * 512;

    float acc[4][8];
    #pragma unroll
    for (int i = 0; i < 4; i++)
        #pragma unroll
        for (int j = 0; j < 8; j++) acc[i][j] = 0.f;

    int pb = (t & 7) * 8;
    int ro = (t >> 3) * 4;
    for (int st = 0; st < 8; st++) {
        int nb = nb0 + st*64;
        __syncthreads();
        for (int i = t; i < 64*64; i += 128) {
            int nn = i & 63, rr = i >> 6;
            Ks[rr][nn] = src[(r0 + rr)*NN + nb + nn];
            Es[rr][nn] = EFw[rr*NN + nb + nn];
        }
        __syncthreads();
        #pragma unroll 4
        for (int nn = 0; nn < 64; nn += 4) {
            float4 rv[4];
            #pragma unroll
            for (int i = 0; i < 4; i++)
                rv[i] = *reinterpret_cast<const float4*>(&Ks[ro + i][nn]);
            #pragma unroll
            for (int j = 0; j < 8; j++) {
                float4 e = *reinterpret_cast<const float4*>(&Es[pb + j][nn]);
                #pragma unroll
                for (int i = 0; i < 4; i++) {
                    acc[i][j] += rv[i].x*e.x + rv[i].y*e.y
                               + rv[i].z*e.z + rv[i].w*e.w;
                }
            }
        }
    }
    #pragma unroll
    for (int i = 0; i < 4; i++)
        #pragma unroll
        for (int j = 0; j < 8; j++)
            g_part[(chunk*256 + rg*64 + ro + i)*PP + pb + j] = acc[i][j];
}

__global__ __launch_bounds__(256) void k2_proj_reduce(const float* __restrict__ EFb)
{
    int idx = blockIdx.x * 256 + threadIdx.x;
    int row = idx >> 6, p = idx & 63;
    float s = 0.f;
    for (int c = 0; c < 64; c++) s += g_part[(c*256 + row)*PP + p];
    s += EFb[p];
    if (row < 128) g_kproj[row*PP + p] = s;
    else           g_vproj[(row - 128)*PP + p] = s;
}

// ---------------- K3a: gram matrix + L2 norms (partial) ----------------
__global__ __launch_bounds__(256) void k3a_gram_partial()
{
    int split = blockIdx.x;
    int bh    = blockIdx.y;
    int t     = threadIdx.x;
    const float* qb = g_q + bh*8*NN;
    const float* kb = g_k + bh*8*NN;

    float v[80];
    #pragma unroll
    for (int i = 0; i < 80; i++) v[i] = 0.f;

    int nend = split*4096 + 4096;
    for (int n = split*4096 + t; n < nend; n += 256) {
        float qv[8], kv[8];
        #pragma unroll
        for (int d = 0; d < 8; d++) { qv[d] = qb[d*NN + n]; kv[d] = kb[d*NN + n]; }
        #pragma unroll
        for (int d = 0; d < 8; d++) {
            v[64 + d] += qv[d]*qv[d];
            v[72 + d] += kv[d]*kv[d];
            #pragma unroll
            for (int e = 0; e < 8; e++) v[d*8 + e] += qv[d]*kv[e];
        }
    }
    __shared__ float wsum[8][80];
    int w = t >> 5, lane = t & 31;
    #pragma unroll
    for (int i = 0; i < 80; i++) {
        float s = v[i];
        #pragma unroll
        for (int o = 16; o > 0; o >>= 1) s += __shfl_xor_sync(0xffffffffu, s, o);
        if (lane == 0) wsum[w][i] = s;
    }
    __syncthreads();
    if (t < 80) {
        float s = 0.f;
        #pragma unroll
        for (int ww = 0; ww < 8; ww++) s += wsum[ww][t];
        g_npart[(split*16 + bh)*80 + t] = s;
    }
}

// ---------------- K3a2: finalize norms + channel-attention softmax ----------------
__global__ __launch_bounds__(128) void k3a_finalize(const float* __restrict__ temp1)
{
    int bh = blockIdx.x;
    int t  = threadIdx.x;
    __shared__ float tot[80];
    __shared__ float qi[8], ki[8];
    if (t < 80) {
        float s = 0.f;
        #pragma unroll
        for (int sp = 0; sp < 8; sp++) s += g_npart[(sp*16 + bh)*80 + t];
        tot[t] = s;
    }
    __syncthreads();
    if (t < 8) {
        float qn = sqrtf(tot[64 + t]);
        float kn = sqrtf(tot[72 + t]);
        qi[t] = 1.0f / fmaxf(qn, 1e-12f);
        ki[t] = 1.0f / fmaxf(kn, 1e-12f);
        g_qinv[bh*8 + t] = qi[t];
    }
    __syncthreads();
    if (t < 8) {
        int h = bh & 3;
        float t1 = temp1[h];
        float sc[8];
        float m = -1e30f;
        #pragma unroll
        for (int e = 0; e < 8; e++) {
            sc[e] = tot[t*8 + e] * qi[t] * ki[e] * t1;
            m = fmaxf(m, sc[e]);
        }
        float sum = 0.f;
        #pragma unroll
        for (int e = 0; e < 8; e++) { sc[e] = __expf(sc[e] - m); sum += sc[e]; }
        float inv = 1.0f / sum;
        #pragma unroll
        for (int e = 0; e < 8; e++) g_attnca[bh*64 + t*8 + e] = sc[e]*inv;
    }
}

// ---------------- K3b: spatial attention per token + channel-attn apply ----------------
__global__ __launch_bounds__(128) void k3b_attn(const float* __restrict__ temp2)
{
    int bh = blockIdx.y;
    int n  = blockIdx.x * 128 + threadIdx.x;
    int h  = bh & 3;
    int t  = threadIdx.x;
    __shared__ float kq[8][64], vp[8][64], A[8][8];
    float t2 = temp2[h];
    for (int i = t; i < 512; i += 128) {
        int d = i >> 6, p = i & 63;
        kq[d][p] = g_qinv[bh*8 + d] * g_kproj[(bh*8 + d)*PP + p] * t2;
        vp[d][p] = g_vproj[(bh*8 + d)*PP + p];
    }
    if (t < 64) A[t >> 3][t & 7] = g_attnca[bh*64 + t];
    __syncthreads();

    int base = bh*8*NN + n;
    float qv[8];
    #pragma unroll
    for (int d = 0; d < 8; d++) qv[d] = g_q[base + d*NN];

    float s[64];
    #pragma unroll
    for (int p = 0; p < 64; p++) s[p] = qv[0]*kq[0][p];
    #pragma unroll
    for (int d = 1; d < 8; d++)
        #pragma unroll
        for (int p = 0; p < 64; p++) s[p] += qv[d]*kq[d][p];

    float m = s[0];
    #pragma unroll
    for (int p = 1; p < 64; p++) m = fmaxf(m, s[p]);
    float sum = 0.f;
    #pragma unroll
    for (int p = 0; p < 64; p++) { s[p] = __expf(s[p] - m); sum += s[p]; }
    float inv = 1.0f / sum;

    #pragma unroll
    for (int d = 0; d < 8; d++) {
        float o = 0.f;
        #pragma unroll
        for (int p = 0; p < 64; p++) o += s[p]*vp[d][p];
        g_xsa[base + d*NN] = o * inv;
    }
    float vv[8];
    #pragma unroll
    for (int e = 0; e < 8; e++) vv[e] = g_vca[base + e*NN];
    #pragma unroll
    for (int d = 0; d < 8; d++) {
        float xc = 0.f;
        #pragma unroll
        for (int e = 0; e < 8; e++) xc += A[d][e]*vv[e];
        g_xca[base + d*NN] = xc;
    }
}

// ---------------- K4: scramble-gather, out1/out2 linears, gamma residual ----------------
__global__ __launch_bounds__(128) void k4_combine(
    const float* __restrict__ o1w, const float* __restrict__ o1b,
    const float* __restrict__ o2w, const float* __restrict__ o2b,
    const float* __restrict__ gamma)
{
    __shared__ float sa[32][33], ca[32][33], xtl[32][33];
    __shared__ float w1[16][32], w2[16][32], b1[16], b2[16], gm[32];
    int b  = blockIdx.x >> 10;
    int t0 = (blockIdx.x & 1023) << 5;
    int t  = threadIdx.x;
    int dd   = t0 >> 12;
    int hh   = (t0 >> 10) & 3;
    int nsrc = (t0 & 1023) << 5;

    const float* sap = g_xsa + ((b*NHEAD + hh)*HDIM + dd)*NN + nsrc;
    for (int i = t; i < 1024; i += 128) sa[i >> 5][i & 31] = sap[i];
    for (int i = t; i < 1024; i += 128) {
        int c = i >> 5, ii = i & 31;
        ca[ii][c] = g_xca[(b*CC + c)*NN + t0 + ii];
    }
    for (int i = t; i < 1024; i += 128) {
        int ii = i >> 5, c = i & 31;
        xtl[ii][c] = g_xt[(b*NN + t0 + ii)*CC + c];
    }
    for (int i = t; i < 512; i += 128) {
        w1[i >> 5][i & 31] = o1w[i];
        w2[i >> 5][i & 31] = o2w[i];
    }
    if (t < 16) { b1[t] = o1b[t]; b2[t] = o2b[t]; }
    if (t < 32) gm[t] = gamma[t];
    __syncthreads();

    int ii = t & 31;
    int cg = t >> 5;
    #pragma unroll
    for (int cc = 0; cc < 8; cc++) {
        int c = cg*8 + cc;
        float val;
        if (c < 16) {
            float s = b1[c];
            #pragma unroll
            for (int k = 0; k < 32; k++) s += sa[ii][k]*w1[c][k];
            val = s;
        } else {
            int j = c - 16;
            float s = b2[j];
            #pragma unroll
            for (int k = 0; k < 32; k++) s += ca[ii][k]*w2[j][k];
            val = s;
        }
        float r = xtl[ii][c] + gm[c]*val;
        g_skip[(b*CC + c)*NN + t0 + ii] = r;
    }
}

// ---------------- conv 3x3x3 + BN (+residual) + LeakyReLU  (scalar, restructured) ----------------
// Block: 128 threads. Thread tile: 8 co x 8 x. Block tile: 32co x 8y x 32x at one z.
// Grid: (4 ygroups, 32 z, 4 batch) = 512 blocks.
// ci in 8 passes of CIP=4; ALL 27 taps of the pass's weights loaded once (2 syncs/pass).
#define CIP 4
#define WS(ci,tap,co) ws[((ci)*27 + (tap))*33 + (co)]
template<int MODE>
__global__ __launch_bounds__(128) void conv3_bn(
    const float* __restrict__ w,  const float* __restrict__ cb,
    const float* __restrict__ bg, const float* __restrict__ bb,
    const float* __restrict__ bm, const float* __restrict__ bv)
{
    __shared__ __align__(16) float xs[CIP][3][10][36];   // 17.3 KB
    __shared__ __align__(16) float ws[CIP*27*33];        // 14.3 KB, pad-33 = conflict-free
    __shared__ float scs[32], bss[32];
    const float* in  = (MODE == 1) ? g_skip : g_y1;
    float*       out = (MODE == 1) ? g_y1   : g_y2;
    const float* res = g_skip;

    int y0 = blockIdx.x * 8;
    int z  = blockIdx.y;
    int b  = blockIdx.z;
    int t  = threadIdx.x;
    if (t < 32) {
        float a = bg[t]*rsqrtf(bv[t] + 1e-5f);
        scs[t] = a;
        bss[t] = (cb[t] - bm[t])*a + bb[t];
    }
    int cg  = t & 3;             // co group: co0 = cg*8
    int xg  = (t >> 2) & 3;      // x group:  xb = xg*8
    int ty  = t >> 4;            // 0..7
    int co0 = cg * 8;
    int xb  = xg * 8;

    float acc[8][8];
    #pragma unroll
    for (int c = 0; c < 8; c++)
        #pragma unroll
        for (int u = 0; u < 8; u++) acc[c][u] = 0.f;

    for (int pass = 0; pass < 8; pass++) {
        int cio = pass * CIP;
        __syncthreads();
        // ---- input tile (coalesced along x) ----
        for (int fl = t; fl < CIP*3*10*34; fl += 128) {
            int xx = fl % 34; int r2 = fl / 34;
            int yy = r2 % 10; r2 /= 10;
            int zz = r2 % 3;  int ci = r2 / 3;
            int zg = z + zz - 1, ygl = y0 + yy - 1, xgc = xx - 1;
            float v = 0.f;
            if ((unsigned)zg < 32u && (unsigned)ygl < 32u && (unsigned)xgc < 32u)
                v = in[(((b*32 + cio + ci)*32 + zg)*32 + ygl)*32 + xgc];
            xs[ci][zz][yy][xx] = v;
        }
        // ---- all 27 taps of this pass's weights, once (tap fastest -> coalesced reads) ----
        for (int fl = t; fl < 32*CIP*27; fl += 128) {
            int tap = fl % 27; int r2 = fl / 27;
            int ci  = r2 & (CIP - 1);
            int co  = r2 >> 2;
            WS(ci, tap, co) = w[(co*32 + cio + ci)*27 + tap];
        }
        __syncthreads();
        // ---- compute: kz,ky rolled (9 iters), ci unrolled ----
        for (int kz = 0; kz < 3; kz++)
        for (int ky = 0; ky < 3; ky++) {
            int tap0 = (kz*3 + ky)*3;
            #pragma unroll
            for (int ci = 0; ci < CIP; ci++) {
                const float* xr = &xs[ci][kz][ty + ky][xb];
                float4 a0 = *reinterpret_cast<const float4*>(xr);
                float4 a1 = *reinterpret_cast<const float4*>(xr + 4);
                float2 a2 = *reinterpret_cast<const float2*>(xr + 8);
                float xv[10] = {a0.x, a0.y, a0.z, a0.w,
                                a1.x, a1.y, a1.z, a1.w,
                                a2.x, a2.y};
                #pragma unroll
                for (int c = 0; c < 8; c++) {
                    float w0 = WS(ci, tap0 + 0, co0 + c);
                    float w1 = WS(ci, tap0 + 1, co0 + c);
                    float w2 = WS(ci, tap0 + 2, co0 + c);
                    #pragma unroll
                    for (int u = 0; u < 8; u++)
                        acc[c][u] += w0*xv[u] + w1*xv[u + 1] + w2*xv[u + 2];
                }
            }
        }
    }
    // ---- epilogue: BN (+res) + LeakyReLU, two float4 stores per co ----
    #pragma unroll
    for (int c = 0; c < 8; c++) {
        int co = co0 + c;
        int base = (((b*32 + co)*32 + z)*32 + (y0 + ty))*32 + xb;
        float a = scs[co], bo = bss[co];
        float f[8];
        #pragma unroll
        for (int u = 0; u < 8; u++) {
            float v = acc[c][u]*a + bo;
            if (MODE == 1) {
                v = (v > 0.f) ? v : 0.01f*v;
            } else {
                v += res[base + u];
                v = (v > 0.f) ? v : 0.01f*v;
            }
            f[u] = v;
        }
        *reinterpret_cast<float4*>(&out[base])     = make_float4(f[0], f[1], f[2], f[3]);
        *reinterpret_cast<float4*>(&out[base + 4]) = make_float4(f[4], f[5], f[6], f[7]);
    }
}

// ---------------- final: 1x1 conv residual ----------------
__global__ __launch_bounds__(256) void k_final(
    const float* __restrict__ wp, const float* __restrict__ bp,
    float* __restrict__ outp)
{
    __shared__ float ys[32][64];
    __shared__ float wsm[32][32];
    __shared__ float bsh[32];
    int b  = blockIdx.x >> 9;
    int n0 = (blockIdx.x & 511) << 6;
    int t  = threadIdx.x;
    for (int i = t; i < 2048; i += 256) {
        int ci = i >> 6, nn = i & 63;
        ys[ci][nn] = g_y2[(b*32 + ci)*NN + n0 + nn];
    }
    for (int i = t; i < 1024; i += 256) wsm[i >> 5][i & 31] = wp[i];
    if (t < 32) bsh[t] = bp[t];
    __syncthreads();
    int nn = t & 63;
    int cg = t >> 6;
    #pragma unroll
    for (int cc = 0; cc < 8; cc++) {
        int co = cg*8 + cc;
        float s = bsh[co];
        #pragma unroll
        for (int ci = 0; ci < 32; ci++) s += wsm[co][ci]*ys[ci][nn];
        int idx = (b*32 + co)*NN + n0 + nn;
        outp[idx] = g_skip[idx] + s;
    }
}

// ---------------- launch ----------------
extern "C" void kernel_launch(void* const* d_in, const int* in_sizes, int n_in,
                              void* d_out, int out_size)
{
    const float* x    = (const float*)d_in[0];
    const float* pos  = (const float*)d_in[1];
    const float* lng  = (const float*)d_in[2];
    const float* lnb  = (const float*)d_in[3];
    const float* gam  = (const float*)d_in[4];
    const float* Wq   = (const float*)d_in[5];
    const float* EFw  = (const float*)d_in[6];
    const float* EFb  = (const float*)d_in[7];
    const float* t1   = (const float*)d_in[8];
    const float* t2   = (const float*)d_in[9];
    const float* o1w  = (const float*)d_in[10];
    const float* o1b  = (const float*)d_in[11];
    const float* o2w  = (const float*)d_in[12];
    const float* o2b  = (const float*)d_in[13];
    const float* c1w  = (const float*)d_in[14];
    const float* c1b  = (const float*)d_in[15];
    const float* b1g  = (const float*)d_in[16];
    const float* b1b  = (const float*)d_in[17];
    const float* b1m  = (const float*)d_in[18];
    const float* b1v  = (const float*)d_in[19];
    const float* c2w  = (const float*)d_in[20];
    const float* c2b  = (const float*)d_in[21];
    const float* b2g  = (const float*)d_in[22];
    const float* b2b  = (const float*)d_in[23];
    const float* b2m  = (const float*)d_in[24];
    const float* b2v  = (const float*)d_in[25];
    const float* cpw  = (const float*)d_in[26];
    const float* cpb  = (const float*)d_in[27];
    float* outp = (float*)d_out;

    k1_tok_ln_qkvv<<<4096, 256>>>(x, pos, lng, lnb, Wq);
    k2_proj_partial<<<dim3(64, 4), 128>>>(EFw);
    k2_proj_reduce<<<64, 256>>>(EFb);
    k3a_gram_partial<<<dim3(8, 16), 256>>>();
    k3a_finalize<<<16, 128>>>(t1);
    k3b_attn<<<dim3(256, 16), 128>>>(t2);
    k4_combine<<<4096, 128>>>(o1w, o1b, o2w, o2b, gam);
    conv3_bn<1><<<dim3(4, 32, 4), 128>>>(c1w, c1b, b1g, b1b, b1m, b1v);
    conv3_bn<2><<<dim3(4, 32, 4), 128>>>(c2w, c2b, b2g, b2b, b2m, b2v);
    k_final<<<2048, 256>>>(cpw, cpb, outp);
}

// round 11
// speedup vs baseline: 1.7624x; 1.4825x over previous
#include <cuda_runtime.h>
#include <cuda_bf16.h>
#include <math.h>
#include <stdint.h>

#define BB 4
#define CC 32
#define NHEAD 4
#define HDIM 8
#define NN 32768
#define PP 64

#define PADN   39304            // 34*34*34
#define GUARD  1536
#define PADSTR (PADN + 2*GUARD) // rows per batch
#define NTILE  308              // ceil(39304/128)

// ---------------- scratch (static device memory; no allocations) ----------------
static __device__ float g_xt  [BB*NN*CC];
static __device__ float g_q   [BB*CC*NN];
static __device__ float g_k   [BB*CC*NN];
static __device__ float g_vca [BB*CC*NN];
static __device__ float g_vsa [BB*CC*NN];
static __device__ float g_part[64*256*PP];
static __device__ float g_kproj[BB*CC*PP];
static __device__ float g_vproj[BB*CC*PP];
static __device__ float g_npart[8*16*80];
static __device__ float g_qinv[BB*CC];
static __device__ float g_attnca[BB*NHEAD*HDIM*HDIM];
static __device__ float g_xsa [BB*CC*NN];
static __device__ float g_xca [BB*CC*NN];
static __device__ float g_skip[BB*CC*NN];      // [b][c][n] for k_final
static __device__ float g_skiptm[BB*NN*CC];    // [b][n][c] for conv2 residual
static __device__ float g_y2tm [BB*NN*CC];     // [b][n][c] conv2 output
// padded token-major conv activations: [b][padtoken][64 bf16 (hi,lo interleaved)]
// zero-initialized; halo/guard rows are NEVER written -> stay zero on every replay.
static __device__ __align__(16) __nv_bfloat16 g_pad1[(size_t)BB*PADSTR*64];
static __device__ __align__(16) __nv_bfloat16 g_pad2[(size_t)BB*PADSTR*64];
// weight images: [tap][chain][co(32)][64 bf16]
static __device__ __align__(16) __nv_bfloat16 g_wimg1[27*2*32*64];
static __device__ __align__(16) __nv_bfloat16 g_wimg2[27*2*32*64];

// ---------------- helpers ----------------
#define SW128(o) ((o) ^ (((o) >> 3) & 0x70))

__device__ __forceinline__ uint32_t smem_u32(const void* p) {
    uint32_t a;
    asm("{ .reg .u64 t; cvta.to.shared.u64 t, %1; cvt.u32.u64 %0, t; }" : "=r"(a) : "l"(p));
    return a;
}
__device__ __forceinline__ void ldmx4(uint32_t* r, uint32_t addr) {
    asm volatile("ldmatrix.sync.aligned.m8n8.x4.shared.b16 {%0,%1,%2,%3}, [%4];"
                 : "=r"(r[0]), "=r"(r[1]), "=r"(r[2]), "=r"(r[3]) : "r"(addr));
}
__device__ __forceinline__ void mma_bf16(float* d, const uint32_t* a, uint32_t b0, uint32_t b1) {
    asm volatile("mma.sync.aligned.m16n8k16.row.col.f32.bf16.bf16.f32 "
                 "{%0,%1,%2,%3}, {%4,%5,%6,%7}, {%8,%9}, {%0,%1,%2,%3};"
                 : "+f"(d[0]), "+f"(d[1]), "+f"(d[2]), "+f"(d[3])
                 : "r"(a[0]), "r"(a[1]), "r"(a[2]), "r"(a[3]), "r"(b0), "r"(b1));
}
__device__ __forceinline__ uint32_t split_pack(float v) {
    __nv_bfloat16 hi = __float2bfloat16_rn(v);
    __nv_bfloat16 lo = __float2bfloat16_rn(v - __bfloat162float(hi));
    __nv_bfloat162 p(hi, lo);
    return *reinterpret_cast<uint32_t*>(&p);
}

// ---------------- K1: transpose+pos, layernorm, QKVV GEMM ----------------
__global__ __launch_bounds__(256) void k1_tok_ln_qkvv(
    const float* __restrict__ x, const float* __restrict__ pos,
    const float* __restrict__ lng, const float* __restrict__ lnb,
    const float* __restrict__ Wq)
{
    __shared__ float xts[32][33];
    __shared__ float Ws[32][128];
    int b  = blockIdx.x >> 10;
    int n0 = (blockIdx.x & 1023) << 5;
    int t  = threadIdx.x;

    for (int i = t; i < 32*128; i += 256) Ws[i >> 7][i & 127] = Wq[i];
    for (int i = t; i < 1024; i += 256) {
        int j = i & 31, c = i >> 5;
        xts[j][c] = x[(b*CC + c)*NN + n0 + j];
    }
    __syncthreads();
    for (int i = t; i < 1024; i += 256) {
        int c = i & 31, j = i >> 5;
        float v = xts[j][c] + pos[(n0 + j)*CC + c];
        xts[j][c] = v;
        g_xt[(b*NN + n0 + j)*CC + c] = v;
    }
    __syncthreads();
    int w = t >> 5, lane = t & 31;
    for (int jj = 0; jj < 4; jj++) {
        int j = w*4 + jj;
        float v = xts[j][lane];
        float s = v, ss = v*v;
        #pragma unroll
        for (int o = 16; o > 0; o >>= 1) {
            s  += __shfl_xor_sync(0xffffffffu, s, o);
            ss += __shfl_xor_sync(0xffffffffu, ss, o);
        }
        float mu  = s * (1.0f/32.0f);
        float var = ss * (1.0f/32.0f) - mu*mu;
        float r   = rsqrtf(var + 1e-5f);
        xts[j][lane] = (v - mu) * r * lng[lane] + lnb[lane];
    }
    __syncthreads();
    float acc[16];
    #pragma unroll
    for (int i = 0; i < 16; i++) acc[i] = 0.f;
    int c0 = w * 16;
    #pragma unroll
    for (int kk = 0; kk < 32; kk++) {
        float xv = xts[lane][kk];
        #pragma unroll
        for (int i = 0; i < 16; i++) acc[i] += xv * Ws[kk][c0 + i];
    }
    #pragma unroll
    for (int i = 0; i < 16; i++) {
        int col   = c0 + i;
        int which = col >> 5;
        int ch    = col & 31;
        float* dst = (which == 0) ? g_q : (which == 1) ? g_k :
                     (which == 2) ? g_vca : g_vsa;
        dst[(b*CC + ch)*NN + n0 + lane] = acc[i];
    }
}

// ---------------- K2: EF projections ----------------
__global__ __launch_bounds__(128) void k2_proj_partial(const float* __restrict__ EFw)
{
    __shared__ __align__(16) float Ks[64][68];
    __shared__ __align__(16) float Es[64][68];
    int chunk = blockIdx.x;
    int rg    = blockIdx.y;
    int t     = threadIdx.x;
    const float* src = (rg < 2) ? g_k : g_vsa;
    int r0  = (rg & 1) * 64;
    int nb0 = chunk * 512;

    float acc[4][8];
    #pragma unroll
    for (int i = 0; i < 4; i++)
        #pragma unroll
        for (int j = 0; j < 8; j++) acc[i][j] = 0.f;

    int pb = (t & 7) * 8;
    int ro = (t >> 3) * 4;
    for (int st = 0; st < 8; st++) {
        int nb = nb0 + st*64;
        __syncthreads();
        for (int i = t; i < 64*64; i += 128) {
            int nn = i & 63, rr = i >> 6;
            Ks[rr][nn] = src[(r0 + rr)*NN + nb + nn];
            Es[rr][nn] = EFw[rr*NN + nb + nn];
        }
        __syncthreads();
        #pragma unroll 4
        for (int nn = 0; nn < 64; nn += 4) {
            float4 rv[4];
            #pragma unroll
            for (int i = 0; i < 4; i++)
                rv[i] = *reinterpret_cast<const float4*>(&Ks[ro + i][nn]);
            #pragma unroll
            for (int j = 0; j < 8; j++) {
                float4 e = *reinterpret_cast<const float4*>(&Es[pb + j][nn]);
                #pragma unroll
                for (int i = 0; i < 4; i++) {
                    acc[i][j] += rv[i].x*e.x + rv[i].y*e.y
                               + rv[i].z*e.z + rv[i].w*e.w;
                }
            }
        }
    }
    #pragma unroll
    for (int i = 0; i < 4; i++)
        #pragma unroll
        for (int j = 0; j < 8; j++)
            g_part[(chunk*256 + rg*64 + ro + i)*PP + pb + j] = acc[i][j];
}

__global__ __launch_bounds__(256) void k2_proj_reduce(const float* __restrict__ EFb)
{
    int idx = blockIdx.x * 256 + threadIdx.x;
    int row = idx >> 6, p = idx & 63;
    float s = 0.f;
    for (int c = 0; c < 64; c++) s += g_part[(c*256 + row)*PP + p];
    s += EFb[p];
    if (row < 128) g_kproj[row*PP + p] = s;
    else           g_vproj[(row - 128)*PP + p] = s;
}

// ---------------- K3a: gram matrix + L2 norms ----------------
__global__ __launch_bounds__(256) void k3a_gram_partial()
{
    int split = blockIdx.x;
    int bh    = blockIdx.y;
    int t     = threadIdx.x;
    const float* qb = g_q + bh*8*NN;
    const float* kb = g_k + bh*8*NN;

    float v[80];
    #pragma unroll
    for (int i = 0; i < 80; i++) v[i] = 0.f;

    int nend = split*4096 + 4096;
    for (int n = split*4096 + t; n < nend; n += 256) {
        float qv[8], kv[8];
        #pragma unroll
        for (int d = 0; d < 8; d++) { qv[d] = qb[d*NN + n]; kv[d] = kb[d*NN + n]; }
        #pragma unroll
        for (int d = 0; d < 8; d++) {
            v[64 + d] += qv[d]*qv[d];
            v[72 + d] += kv[d]*kv[d];
            #pragma unroll
            for (int e = 0; e < 8; e++) v[d*8 + e] += qv[d]*kv[e];
        }
    }
    __shared__ float wsum[8][80];
    int w = t >> 5, lane = t & 31;
    #pragma unroll
    for (int i = 0; i < 80; i++) {
        float s = v[i];
        #pragma unroll
        for (int o = 16; o > 0; o >>= 1) s += __shfl_xor_sync(0xffffffffu, s, o);
        if (lane == 0) wsum[w][i] = s;
    }
    __syncthreads();
    if (t < 80) {
        float s = 0.f;
        #pragma unroll
        for (int ww = 0; ww < 8; ww++) s += wsum[ww][t];
        g_npart[(split*16 + bh)*80 + t] = s;
    }
}

__global__ __launch_bounds__(128) void k3a_finalize(const float* __restrict__ temp1)
{
    int bh = blockIdx.x;
    int t  = threadIdx.x;
    __shared__ float tot[80];
    __shared__ float qi[8], ki[8];
    if (t < 80) {
        float s = 0.f;
        #pragma unroll
        for (int sp = 0; sp < 8; sp++) s += g_npart[(sp*16 + bh)*80 + t];
        tot[t] = s;
    }
    __syncthreads();
    if (t < 8) {
        float qn = sqrtf(tot[64 + t]);
        float kn = sqrtf(tot[72 + t]);
        qi[t] = 1.0f / fmaxf(qn, 1e-12f);
        ki[t] = 1.0f / fmaxf(kn, 1e-12f);
        g_qinv[bh*8 + t] = qi[t];
    }
    __syncthreads();
    if (t < 8) {
        int h = bh & 3;
        float t1 = temp1[h];
        float sc[8];
        float m = -1e30f;
        #pragma unroll
        for (int e = 0; e < 8; e++) {
            sc[e] = tot[t*8 + e] * qi[t] * ki[e] * t1;
            m = fmaxf(m, sc[e]);
        }
        float sum = 0.f;
        #pragma unroll
        for (int e = 0; e < 8; e++) { sc[e] = __expf(sc[e] - m); sum += sc[e]; }
        float inv = 1.0f / sum;
        #pragma unroll
        for (int e = 0; e < 8; e++) g_attnca[bh*64 + t*8 + e] = sc[e]*inv;
    }
}

// ---------------- K3b ----------------
__global__ __launch_bounds__(128) void k3b_attn(const float* __restrict__ temp2)
{
    int bh = blockIdx.y;
    int n  = blockIdx.x * 128 + threadIdx.x;
    int h  = bh & 3;
    int t  = threadIdx.x;
    __shared__ float kq[8][64], vp[8][64], A[8][8];
    float t2 = temp2[h];
    for (int i = t; i < 512; i += 128) {
        int d = i >> 6, p = i & 63;
        kq[d][p] = g_qinv[bh*8 + d] * g_kproj[(bh*8 + d)*PP + p] * t2;
        vp[d][p] = g_vproj[(bh*8 + d)*PP + p];
    }
    if (t < 64) A[t >> 3][t & 7] = g_attnca[bh*64 + t];
    __syncthreads();

    int base = bh*8*NN + n;
    float qv[8];
    #pragma unroll
    for (int d = 0; d < 8; d++) qv[d] = g_q[base + d*NN];

    float s[64];
    #pragma unroll
    for (int p = 0; p < 64; p++) s[p] = qv[0]*kq[0][p];
    #pragma unroll
    for (int d = 1; d < 8; d++)
        #pragma unroll
        for (int p = 0; p < 64; p++) s[p] += qv[d]*kq[d][p];

    float m = s[0];
    #pragma unroll
    for (int p = 1; p < 64; p++) m = fmaxf(m, s[p]);
    float sum = 0.f;
    #pragma unroll
    for (int p = 0; p < 64; p++) { s[p] = __expf(s[p] - m); sum += s[p]; }
    float inv = 1.0f / sum;

    #pragma unroll
    for (int d = 0; d < 8; d++) {
        float o = 0.f;
        #pragma unroll
        for (int p = 0; p < 64; p++) o += s[p]*vp[d][p];
        g_xsa[base + d*NN] = o * inv;
    }
    float vv[8];
    #pragma unroll
    for (int e = 0; e < 8; e++) vv[e] = g_vca[base + e*NN];
    #pragma unroll
    for (int d = 0; d < 8; d++) {
        float xc = 0.f;
        #pragma unroll
        for (int e = 0; e < 8; e++) xc += A[d][e]*vv[e];
        g_xca[base + d*NN] = xc;
    }
}

// ---------------- K4: combine; write skip ([c][n] and [n][c]) + pad1 (bf16 pairs) ----------------
__global__ __launch_bounds__(128) void k4_combine(
    const float* __restrict__ o1w, const float* __restrict__ o1b,
    const float* __restrict__ o2w, const float* __restrict__ o2b,
    const float* __restrict__ gamma)
{
    __shared__ float sa[32][33], ca[32][33], xtl[32][33], resm[32][33];
    __shared__ float w1[16][32], w2[16][32], b1[16], b2[16], gm[32];
    int b  = blockIdx.x >> 10;
    int t0 = (blockIdx.x & 1023) << 5;
    int t  = threadIdx.x;
    int dd   = t0 >> 12;
    int hh   = (t0 >> 10) & 3;
    int nsrc = (t0 & 1023) << 5;

    const float* sap = g_xsa + ((b*NHEAD + hh)*HDIM + dd)*NN + nsrc;
    for (int i = t; i < 1024; i += 128) sa[i >> 5][i & 31] = sap[i];
    for (int i = t; i < 1024; i += 128) {
        int c = i >> 5, ii = i & 31;
        ca[ii][c] = g_xca[(b*CC + c)*NN + t0 + ii];
    }
    for (int i = t; i < 1024; i += 128) {
        int ii = i >> 5, c = i & 31;
        xtl[ii][c] = g_xt[(b*NN + t0 + ii)*CC + c];
    }
    for (int i = t; i < 512; i += 128) {
        w1[i >> 5][i & 31] = o1w[i];
        w2[i >> 5][i & 31] = o2w[i];
    }
    if (t < 16) { b1[t] = o1b[t]; b2[t] = o2b[t]; }
    if (t < 32) gm[t] = gamma[t];
    __syncthreads();

    int ii = t & 31;
    int cg = t >> 5;
    #pragma unroll
    for (int cc = 0; cc < 8; cc++) {
        int c = cg*8 + cc;
        float val;
        if (c < 16) {
            float s = b1[c];
            #pragma unroll
            for (int k = 0; k < 32; k++) s += sa[ii][k]*w1[c][k];
            val = s;
        } else {
            int j = c - 16;
            float s = b2[j];
            #pragma unroll
            for (int k = 0; k < 32; k++) s += ca[ii][k]*w2[j][k];
            val = s;
        }
        float r = xtl[ii][c] + gm[c]*val;
        resm[ii][c] = r;
        g_skip[(b*CC + c)*NN + t0 + ii] = r;
    }
    __syncthreads();
    // token-major writes
    int tok = t >> 2, cgp = t & 3;
    int n   = t0 + tok;
    // skip token-major
    {
        float4 v0 = make_float4(resm[tok][cgp*8],   resm[tok][cgp*8+1],
                                resm[tok][cgp*8+2], resm[tok][cgp*8+3]);
        float4 v1 = make_float4(resm[tok][cgp*8+4], resm[tok][cgp*8+5],
                                resm[tok][cgp*8+6], resm[tok][cgp*8+7]);
        float4* d = reinterpret_cast<float4*>(g_skiptm + ((size_t)b*NN + n)*CC + cgp*8);
        d[0] = v0; d[1] = v1;
    }
    // pad1 (hi,lo) bf16 pairs
    int npad = ((n >> 10) + 1)*1156 + (((n >> 5) & 31) + 1)*34 + (n & 31) + 1;
    uint32_t rw[8];
    #pragma unroll
    for (int c = 0; c < 8; c++) rw[c] = split_pack(resm[tok][cgp*8 + c]);
    float4* dst = reinterpret_cast<float4*>(
        g_pad1 + ((size_t)b*PADSTR + GUARD + npad)*64 + cgp*16);
    dst[0] = make_float4(__uint_as_float(rw[0]), __uint_as_float(rw[1]),
                         __uint_as_float(rw[2]), __uint_as_float(rw[3]));
    dst[1] = make_float4(__uint_as_float(rw[4]), __uint_as_float(rw[5]),
                         __uint_as_float(rw[6]), __uint_as_float(rw[7]));
}

// ---------------- weight prep: hi/lo bf16 images ----------------
__global__ __launch_bounds__(256) void kw_prep(const float* __restrict__ c1w,
                                               const float* __restrict__ c2w)
{
    int i = blockIdx.x*256 + threadIdx.x;      // 0 .. 2*27648
    if (i >= 2*27648) return;
    int which = (i >= 27648);
    int j = i - which*27648;                   // j = (co*32+ci)*27 + tap
    const float* w = which ? c2w : c1w;
    __nv_bfloat16* out = which ? g_wimg2 : g_wimg1;
    int tap = j % 27; int r = j / 27; int ci = r & 31; int co = r >> 5;
    float v = w[j];
    __nv_bfloat16 hi = __float2bfloat16_rn(v);
    __nv_bfloat16 lo = __float2bfloat16_rn(v - __bfloat162float(hi));
    __nv_bfloat16 z  = __float2bfloat16(0.f);
    out[((tap*2 + 0)*32 + co)*64 + 2*ci]     = hi;
    out[((tap*2 + 0)*32 + co)*64 + 2*ci + 1] = hi;
    out[((tap*2 + 1)*32 + co)*64 + 2*ci]     = lo;
    out[((tap*2 + 1)*32 + co)*64 + 2*ci + 1] = z;
}

// ---------------- conv via mma.sync: 27 taps x (M=128,N=32,K=64) bf16-split ----------------
// MODE 1: in=g_pad1 -> BN+lrelu -> g_pad2 (padded bf16 pairs)
// MODE 2: in=g_pad2 -> BN + skiptm residual + lrelu -> g_y2tm (fp32 [n][c])
template<int MODE>
__global__ __launch_bounds__(128) void conv_mma(
    const float* __restrict__ cb, const float* __restrict__ bg,
    const float* __restrict__ bb, const float* __restrict__ bm,
    const float* __restrict__ bv)
{
    __shared__ __align__(128) __nv_bfloat16 Asm[128*64];   // 16KB, rows=token, 128B each
    __shared__ __align__(128) __nv_bfloat16 Bsm[2*32*64];  // 8KB, [chain][n][k]
    __shared__ float scs[32], bss[32];

    const __nv_bfloat16* gA = (MODE == 1) ? g_pad1 : g_pad2;
    const __nv_bfloat16* gW = (MODE == 1) ? g_wimg1 : g_wimg2;

    int t = threadIdx.x, warp = t >> 5, lane = t & 31;
    int base = blockIdx.x * 128;
    int b    = blockIdx.y;
    long volr = (long)b*PADSTR + GUARD;

    if (t < 32) {
        float a = bg[t]*rsqrtf(bv[t] + 1e-5f);
        scs[t] = a;
        bss[t] = (cb[t] - bm[t])*a + bb[t];
    }

    uint32_t Abase = smem_u32(Asm), Bbase = smem_u32(Bsm);
    float acc[2][4][4];
    #pragma unroll
    for (int mt = 0; mt < 2; mt++)
        #pragma unroll
        for (int nb = 0; nb < 4; nb++)
            #pragma unroll
            for (int j = 0; j < 4; j++) acc[mt][nb][j] = 0.f;

    // per-lane ldmatrix address components (constant over taps)
    int a_rl = (lane & 7) + ((lane >> 3) & 1)*8;    // 0..15
    int a_cs = lane >> 4;                            // 0,1
    int b_rn = (lane & 7) + ((lane >> 4) << 3);      // 0..15
    int b_cs = (lane >> 3) & 1;                      // 0,1

    for (int tap = 0; tap < 27; tap++) {
        __syncthreads();
        int kz = tap/9, ky = (tap/3)%3, kx = tap%3;
        int dlt = (kz - 1)*1156 + (ky - 1)*34 + (kx - 1);
        long rbase = volr + base + dlt;
        // stage A: 128 rows x 128B, SW128 swizzle
        #pragma unroll
        for (int idx = t; idx < 1024; idx += 128) {
            int r = idx >> 3, c16 = idx & 7;
            float4 v = *reinterpret_cast<const float4*>(gA + (rbase + r)*64 + c16*8);
            *reinterpret_cast<float4*>(
                reinterpret_cast<char*>(Asm) + SW128(r*128 + c16*16)) = v;
        }
        // stage B: 2 chains x 32 rows x 128B
        #pragma unroll
        for (int idx = t; idx < 512; idx += 128) {
            int row = idx >> 3, c16 = idx & 7;   // row = chain*32 + n
            float4 v = *reinterpret_cast<const float4*>(gW + ((size_t)tap*64 + row)*64 + c16*8);
            *reinterpret_cast<float4*>(
                reinterpret_cast<char*>(Bsm) + ((row >> 5) << 12)
                + SW128((row & 31)*128 + c16*16)) = v;
        }
        __syncthreads();
        #pragma unroll
        for (int ks = 0; ks < 4; ks++) {
            uint32_t a[2][4];
            #pragma unroll
            for (int mt = 0; mt < 2; mt++) {
                int row = warp*32 + mt*16 + a_rl;
                ldmx4(a[mt], Abase + SW128(row*128 + (2*ks + a_cs)*16));
            }
            uint32_t bf[2][8];
            #pragma unroll
            for (int chain = 0; chain < 2; chain++)
                #pragma unroll
                for (int np = 0; np < 2; np++) {
                    int rn = np*16 + b_rn;
                    ldmx4(&bf[chain][np*4],
                          Bbase + (chain << 12) + SW128(rn*128 + (2*ks + b_cs)*16));
                }
            #pragma unroll
            for (int mt = 0; mt < 2; mt++)
                #pragma unroll
                for (int nb = 0; nb < 4; nb++) {
                    int bi = (nb >> 1)*4 + (nb & 1)*2;
                    mma_bf16(acc[mt][nb], a[mt], bf[0][bi], bf[0][bi + 1]);
                    mma_bf16(acc[mt][nb], a[mt], bf[1][bi], bf[1][bi + 1]);
                }
        }
    }

    // ---- epilogue ----
    int cl = lane & 3;
    #pragma unroll
    for (int mt = 0; mt < 2; mt++)
        #pragma unroll
        for (int half = 0; half < 2; half++) {
            int m = base + warp*32 + mt*16 + (lane >> 2) + half*8;  // padded token
            int zp = m / 1156; int rem = m - zp*1156;
            int yp = rem / 34; int xp = rem - yp*34;
            if (zp < 1 || zp > 32 || yp < 1 || yp > 32 || xp < 1 || xp > 32) continue;
            if (MODE == 1) {
                __nv_bfloat16* dst = g_pad2 + (volr + m)*64;
                #pragma unroll
                for (int nb = 0; nb < 4; nb++) {
                    int co = nb*8 + 2*cl;
                    float v0 = acc[mt][nb][half*2]    *scs[co]   + bss[co];
                    float v1 = acc[mt][nb][half*2 + 1]*scs[co+1] + bss[co+1];
                    v0 = (v0 > 0.f) ? v0 : 0.01f*v0;
                    v1 = (v1 > 0.f) ? v1 : 0.01f*v1;
                    uint2 w2 = make_uint2(split_pack(v0), split_pack(v1));
                    *reinterpret_cast<uint2*>(dst + co*2) = w2;
                }
            } else {
                int n = (zp - 1)*1024 + (yp - 1)*32 + (xp - 1);
                const float* sk = g_skiptm + ((size_t)b*NN + n)*CC;
                float* dst = g_y2tm + ((size_t)b*NN + n)*CC;
                #pragma unroll
                for (int nb = 0; nb < 4; nb++) {
                    int co = nb*8 + 2*cl;
                    float2 s = *reinterpret_cast<const float2*>(sk + co);
                    float v0 = acc[mt][nb][half*2]    *scs[co]   + bss[co]   + s.x;
                    float v1 = acc[mt][nb][half*2 + 1]*scs[co+1] + bss[co+1] + s.y;
                    v0 = (v0 > 0.f) ? v0 : 0.01f*v0;
                    v1 = (v1 > 0.f) ? v1 : 0.01f*v1;
                    *reinterpret_cast<float2*>(dst + co) = make_float2(v0, v1);
                }
            }
        }
}

// ---------------- final: 1x1 conv residual (reads token-major y2) ----------------
__global__ __launch_bounds__(256) void k_final(
    const float* __restrict__ wp, const float* __restrict__ bp,
    float* __restrict__ outp)
{
    __shared__ float ys[64][33];
    __shared__ float wsm[32][32];
    __shared__ float bsh[32];
    int b  = blockIdx.x >> 9;
    int n0 = (blockIdx.x & 511) << 6;
    int t  = threadIdx.x;
    for (int i = t; i < 2048; i += 256) {
        int nn = i >> 5, ci = i & 31;
        ys[nn][ci] = g_y2tm[((size_t)b*NN + n0 + nn)*CC + ci];
    }
    for (int i = t; i < 1024; i += 256) wsm[i >> 5][i & 31] = wp[i];
    if (t < 32) bsh[t] = bp[t];
    __syncthreads();
    int nn = t & 63;
    int cg = t >> 6;
    #pragma unroll
    for (int cc = 0; cc < 8; cc++) {
        int co = cg*8 + cc;
        float s = bsh[co];
        #pragma unroll
        for (int ci = 0; ci < 32; ci++) s += wsm[co][ci]*ys[nn][ci];
        int idx = (b*32 + co)*NN + n0 + nn;
        outp[idx] = g_skip[idx] + s;
    }
}

// ---------------- launch ----------------
extern "C" void kernel_launch(void* const* d_in, const int* in_sizes, int n_in,
                              void* d_out, int out_size)
{
    const float* x    = (const float*)d_in[0];
    const float* pos  = (const float*)d_in[1];
    const float* lng  = (const float*)d_in[2];
    const float* lnb  = (const float*)d_in[3];
    const float* gam  = (const float*)d_in[4];
    const float* Wq   = (const float*)d_in[5];
    const float* EFw  = (const float*)d_in[6];
    const float* EFb  = (const float*)d_in[7];
    const float* t1   = (const float*)d_in[8];
    const float* t2   = (const float*)d_in[9];
    const float* o1w  = (const float*)d_in[10];
    const float* o1b  = (const float*)d_in[11];
    const float* o2w  = (const float*)d_in[12];
    const float* o2b  = (const float*)d_in[13];
    const float* c1w  = (const float*)d_in[14];
    const float* c1b  = (const float*)d_in[15];
    const float* b1g  = (const float*)d_in[16];
    const float* b1b  = (const float*)d_in[17];
    const float* b1m  = (const float*)d_in[18];
    const float* b1v  = (const float*)d_in[19];
    const float* c2w  = (const float*)d_in[20];
    const float* c2b  = (const float*)d_in[21];
    const float* b2g  = (const float*)d_in[22];
    const float* b2b  = (const float*)d_in[23];
    const float* b2m  = (const float*)d_in[24];
    const float* b2v  = (const float*)d_in[25];
    const float* cpw  = (const float*)d_in[26];
    const float* cpb  = (const float*)d_in[27];
    float* outp = (float*)d_out;

    kw_prep<<<216, 256>>>(c1w, c2w);
    k1_tok_ln_qkvv<<<4096, 256>>>(x, pos, lng, lnb, Wq);
    k2_proj_partial<<<dim3(64, 4), 128>>>(EFw);
    k2_proj_reduce<<<64, 256>>>(EFb);
    k3a_gram_partial<<<dim3(8, 16), 256>>>();
    k3a_finalize<<<16, 128>>>(t1);
    k3b_attn<<<dim3(256, 16), 128>>>(t2);
    k4_combine<<<4096, 128>>>(o1w, o1b, o2w, o2b, gam);
    conv_mma<1><<<dim3(NTILE, BB), 128>>>(c1b, b1g, b1b, b1m, b1v);
    conv_mma<2><<<dim3(NTILE, BB), 128>>>(c2b, b2g, b2b, b2m, b2v);
    k_final<<<2048, 256>>>(cpw, cpb, outp);
}

// round 12
// speedup vs baseline: 1.7688x; 1.0036x over previous
#include <cuda_runtime.h>
#include <cuda_bf16.h>
#include <math.h>
#include <stdint.h>

#define BB 4
#define CC 32
#define NHEAD 4
#define HDIM 8
#define NN 32768
#define PP 64

#define PADN   39304            // 34*34*34
#define GUARD  1536
#define PADSTR (PADN + 2*GUARD) // rows per batch
#define NTILE2 154              // ceil(39304/256)

// ---------------- scratch (static device memory; no allocations) ----------------
static __device__ float g_xt  [BB*NN*CC];
static __device__ float g_q   [BB*CC*NN];
static __device__ float g_k   [BB*CC*NN];
static __device__ float g_vca [BB*CC*NN];
static __device__ float g_vsa [BB*CC*NN];
static __device__ float g_part[64*256*PP];
static __device__ float g_kproj[BB*CC*PP];
static __device__ float g_vproj[BB*CC*PP];
static __device__ float g_npart[8*16*80];
static __device__ float g_qinv[BB*CC];
static __device__ float g_attnca[BB*NHEAD*HDIM*HDIM];
static __device__ float g_xsa [BB*CC*NN];
static __device__ float g_xca [BB*CC*NN];
static __device__ float g_skip[BB*CC*NN];      // [b][c][n] for k_final
static __device__ float g_skiptm[BB*NN*CC];    // [b][n][c] for conv2 residual
static __device__ float g_y2tm [BB*NN*CC];     // [b][n][c] conv2 output
// padded token-major conv activations: [b][padtoken][64 bf16 (hi,lo interleaved)]
static __device__ __align__(16) __nv_bfloat16 g_pad1[(size_t)BB*PADSTR*64];
static __device__ __align__(16) __nv_bfloat16 g_pad2[(size_t)BB*PADSTR*64];
// weight images: [tap][chain][co(32)][64 bf16]
static __device__ __align__(16) __nv_bfloat16 g_wimg1[27*2*32*64];
static __device__ __align__(16) __nv_bfloat16 g_wimg2[27*2*32*64];

// ---------------- helpers ----------------
#define SW128(o) ((o) ^ (((o) >> 3) & 0x70))

__device__ __forceinline__ uint32_t smem_u32(const void* p) {
    uint32_t a;
    asm("{ .reg .u64 t; cvta.to.shared.u64 t, %1; cvt.u32.u64 %0, t; }" : "=r"(a) : "l"(p));
    return a;
}
__device__ __forceinline__ void ldmx4(uint32_t* r, uint32_t addr) {
    asm volatile("ldmatrix.sync.aligned.m8n8.x4.shared.b16 {%0,%1,%2,%3}, [%4];"
                 : "=r"(r[0]), "=r"(r[1]), "=r"(r[2]), "=r"(r[3]) : "r"(addr));
}
__device__ __forceinline__ void mma_bf16(float* d, const uint32_t* a, uint32_t b0, uint32_t b1) {
    asm volatile("mma.sync.aligned.m16n8k16.row.col.f32.bf16.bf16.f32 "
                 "{%0,%1,%2,%3}, {%4,%5,%6,%7}, {%8,%9}, {%0,%1,%2,%3};"
                 : "+f"(d[0]), "+f"(d[1]), "+f"(d[2]), "+f"(d[3])
                 : "r"(a[0]), "r"(a[1]), "r"(a[2]), "r"(a[3]), "r"(b0), "r"(b1));
}
__device__ __forceinline__ uint32_t split_pack(float v) {
    __nv_bfloat16 hi = __float2bfloat16_rn(v);
    __nv_bfloat16 lo = __float2bfloat16_rn(v - __bfloat162float(hi));
    __nv_bfloat162 p(hi, lo);
    return *reinterpret_cast<uint32_t*>(&p);
}

// ---------------- K1: transpose+pos, layernorm, QKVV GEMM ----------------
__global__ __launch_bounds__(256) void k1_tok_ln_qkvv(
    const float* __restrict__ x, const float* __restrict__ pos,
    const float* __restrict__ lng, const float* __restrict__ lnb,
    const float* __restrict__ Wq)
{
    __shared__ float xts[32][33];
    __shared__ float Ws[32][128];
    int b  = blockIdx.x >> 10;
    int n0 = (blockIdx.x & 1023) << 5;
    int t  = threadIdx.x;

    for (int i = t; i < 32*128; i += 256) Ws[i >> 7][i & 127] = Wq[i];
    for (int i = t; i < 1024; i += 256) {
        int j = i & 31, c = i >> 5;
        xts[j][c] = x[(b*CC + c)*NN + n0 + j];
    }
    __syncthreads();
    for (int i = t; i < 1024; i += 256) {
        int c = i & 31, j = i >> 5;
        float v = xts[j][c] + pos[(n0 + j)*CC + c];
        xts[j][c] = v;
        g_xt[(b*NN + n0 + j)*CC + c] = v;
    }
    __syncthreads();
    int w = t >> 5, lane = t & 31;
    for (int jj = 0; jj < 4; jj++) {
        int j = w*4 + jj;
        float v = xts[j][lane];
        float s = v, ss = v*v;
        #pragma unroll
        for (int o = 16; o > 0; o >>= 1) {
            s  += __shfl_xor_sync(0xffffffffu, s, o);
            ss += __shfl_xor_sync(0xffffffffu, ss, o);
        }
        float mu  = s * (1.0f/32.0f);
        float var = ss * (1.0f/32.0f) - mu*mu;
        float r   = rsqrtf(var + 1e-5f);
        xts[j][lane] = (v - mu) * r * lng[lane] + lnb[lane];
    }
    __syncthreads();
    float acc[16];
    #pragma unroll
    for (int i = 0; i < 16; i++) acc[i] = 0.f;
    int c0 = w * 16;
    #pragma unroll
    for (int kk = 0; kk < 32; kk++) {
        float xv = xts[lane][kk];
        #pragma unroll
        for (int i = 0; i < 16; i++) acc[i] += xv * Ws[kk][c0 + i];
    }
    #pragma unroll
    for (int i = 0; i < 16; i++) {
        int col   = c0 + i;
        int which = col >> 5;
        int ch    = col & 31;
        float* dst = (which == 0) ? g_q : (which == 1) ? g_k :
                     (which == 2) ? g_vca : g_vsa;
        dst[(b*CC + ch)*NN + n0 + lane] = acc[i];
    }
}

// ---------------- K2: EF projections ----------------
__global__ __launch_bounds__(128) void k2_proj_partial(const float* __restrict__ EFw)
{
    __shared__ __align__(16) float Ks[64][68];
    __shared__ __align__(16) float Es[64][68];
    int chunk = blockIdx.x;
    int rg    = blockIdx.y;
    int t     = threadIdx.x;
    const float* src = (rg < 2) ? g_k : g_vsa;
    int r0  = (rg & 1) * 64;
    int nb0 = chunk * 512;

    float acc[4][8];
    #pragma unroll
    for (int i = 0; i < 4; i++)
        #pragma unroll
        for (int j = 0; j < 8; j++) acc[i][j] = 0.f;

    int pb = (t & 7) * 8;
    int ro = (t >> 3) * 4;
    for (int st = 0; st < 8; st++) {
        int nb = nb0 + st*64;
        __syncthreads();
        for (int i = t; i < 64*64; i += 128) {
            int nn = i & 63, rr = i >> 6;
            Ks[rr][nn] = src[(r0 + rr)*NN + nb + nn];
            Es[rr][nn] = EFw[rr*NN + nb + nn];
        }
        __syncthreads();
        #pragma unroll 4
        for (int nn = 0; nn < 64; nn += 4) {
            float4 rv[4];
            #pragma unroll
            for (int i = 0; i < 4; i++)
                rv[i] = *reinterpret_cast<const float4*>(&Ks[ro + i][nn]);
            #pragma unroll
            for (int j = 0; j < 8; j++) {
                float4 e = *reinterpret_cast<const float4*>(&Es[pb + j][nn]);
                #pragma unroll
                for (int i = 0; i < 4; i++) {
                    acc[i][j] += rv[i].x*e.x + rv[i].y*e.y
                               + rv[i].z*e.z + rv[i].w*e.w;
                }
            }
        }
    }
    #pragma unroll
    for (int i = 0; i < 4; i++)
        #pragma unroll
        for (int j = 0; j < 8; j++)
            g_part[(chunk*256 + rg*64 + ro + i)*PP + pb + j] = acc[i][j];
}

__global__ __launch_bounds__(256) void k2_proj_reduce(const float* __restrict__ EFb)
{
    int idx = blockIdx.x * 256 + threadIdx.x;
    int row = idx >> 6, p = idx & 63;
    float s = 0.f;
    for (int c = 0; c < 64; c++) s += g_part[(c*256 + row)*PP + p];
    s += EFb[p];
    if (row < 128) g_kproj[row*PP + p] = s;
    else           g_vproj[(row - 128)*PP + p] = s;
}

// ---------------- K3a: gram matrix + L2 norms ----------------
__global__ __launch_bounds__(256) void k3a_gram_partial()
{
    int split = blockIdx.x;
    int bh    = blockIdx.y;
    int t     = threadIdx.x;
    const float* qb = g_q + bh*8*NN;
    const float* kb = g_k + bh*8*NN;

    float v[80];
    #pragma unroll
    for (int i = 0; i < 80; i++) v[i] = 0.f;

    int nend = split*4096 + 4096;
    for (int n = split*4096 + t; n < nend; n += 256) {
        float qv[8], kv[8];
        #pragma unroll
        for (int d = 0; d < 8; d++) { qv[d] = qb[d*NN + n]; kv[d] = kb[d*NN + n]; }
        #pragma unroll
        for (int d = 0; d < 8; d++) {
            v[64 + d] += qv[d]*qv[d];
            v[72 + d] += kv[d]*kv[d];
            #pragma unroll
            for (int e = 0; e < 8; e++) v[d*8 + e] += qv[d]*kv[e];
        }
    }
    __shared__ float wsum[8][80];
    int w = t >> 5, lane = t & 31;
    #pragma unroll
    for (int i = 0; i < 80; i++) {
        float s = v[i];
        #pragma unroll
        for (int o = 16; o > 0; o >>= 1) s += __shfl_xor_sync(0xffffffffu, s, o);
        if (lane == 0) wsum[w][i] = s;
    }
    __syncthreads();
    if (t < 80) {
        float s = 0.f;
        #pragma unroll
        for (int ww = 0; ww < 8; ww++) s += wsum[ww][t];
        g_npart[(split*16 + bh)*80 + t] = s;
    }
}

__global__ __launch_bounds__(128) void k3a_finalize(const float* __restrict__ temp1)
{
    int bh = blockIdx.x;
    int t  = threadIdx.x;
    __shared__ float tot[80];
    __shared__ float qi[8], ki[8];
    if (t < 80) {
        float s = 0.f;
        #pragma unroll
        for (int sp = 0; sp < 8; sp++) s += g_npart[(sp*16 + bh)*80 + t];
        tot[t] = s;
    }
    __syncthreads();
    if (t < 8) {
        float qn = sqrtf(tot[64 + t]);
        float kn = sqrtf(tot[72 + t]);
        qi[t] = 1.0f / fmaxf(qn, 1e-12f);
        ki[t] = 1.0f / fmaxf(kn, 1e-12f);
        g_qinv[bh*8 + t] = qi[t];
    }
    __syncthreads();
    if (t < 8) {
        int h = bh & 3;
        float t1 = temp1[h];
        float sc[8];
        float m = -1e30f;
        #pragma unroll
        for (int e = 0; e < 8; e++) {
            sc[e] = tot[t*8 + e] * qi[t] * ki[e] * t1;
            m = fmaxf(m, sc[e]);
        }
        float sum = 0.f;
        #pragma unroll
        for (int e = 0; e < 8; e++) { sc[e] = __expf(sc[e] - m); sum += sc[e]; }
        float inv = 1.0f / sum;
        #pragma unroll
        for (int e = 0; e < 8; e++) g_attnca[bh*64 + t*8 + e] = sc[e]*inv;
    }
}

// ---------------- K3b ----------------
__global__ __launch_bounds__(128) void k3b_attn(const float* __restrict__ temp2)
{
    int bh = blockIdx.y;
    int n  = blockIdx.x * 128 + threadIdx.x;
    int h  = bh & 3;
    int t  = threadIdx.x;
    __shared__ float kq[8][64], vp[8][64], A[8][8];
    float t2 = temp2[h];
    for (int i = t; i < 512; i += 128) {
        int d = i >> 6, p = i & 63;
        kq[d][p] = g_qinv[bh*8 + d] * g_kproj[(bh*8 + d)*PP + p] * t2;
        vp[d][p] = g_vproj[(bh*8 + d)*PP + p];
    }
    if (t < 64) A[t >> 3][t & 7] = g_attnca[bh*64 + t];
    __syncthreads();

    int base = bh*8*NN + n;
    float qv[8];
    #pragma unroll
    for (int d = 0; d < 8; d++) qv[d] = g_q[base + d*NN];

    float s[64];
    #pragma unroll
    for (int p = 0; p < 64; p++) s[p] = qv[0]*kq[0][p];
    #pragma unroll
    for (int d = 1; d < 8; d++)
        #pragma unroll
        for (int p = 0; p < 64; p++) s[p] += qv[d]*kq[d][p];

    float m = s[0];
    #pragma unroll
    for (int p = 1; p < 64; p++) m = fmaxf(m, s[p]);
    float sum = 0.f;
    #pragma unroll
    for (int p = 0; p < 64; p++) { s[p] = __expf(s[p] - m); sum += s[p]; }
    float inv = 1.0f / sum;

    #pragma unroll
    for (int d = 0; d < 8; d++) {
        float o = 0.f;
        #pragma unroll
        for (int p = 0; p < 64; p++) o += s[p]*vp[d][p];
        g_xsa[base + d*NN] = o * inv;
    }
    float vv[8];
    #pragma unroll
    for (int e = 0; e < 8; e++) vv[e] = g_vca[base + e*NN];
    #pragma unroll
    for (int d = 0; d < 8; d++) {
        float xc = 0.f;
        #pragma unroll
        for (int e = 0; e < 8; e++) xc += A[d][e]*vv[e];
        g_xca[base + d*NN] = xc;
    }
}

// ---------------- K4: combine; write skip ([c][n] and [n][c]) + pad1 (bf16 pairs) ----------------
__global__ __launch_bounds__(128) void k4_combine(
    const float* __restrict__ o1w, const float* __restrict__ o1b,
    const float* __restrict__ o2w, const float* __restrict__ o2b,
    const float* __restrict__ gamma)
{
    __shared__ float sa[32][33], ca[32][33], xtl[32][33], resm[32][33];
    __shared__ float w1[16][32], w2[16][32], b1[16], b2[16], gm[32];
    int b  = blockIdx.x >> 10;
    int t0 = (blockIdx.x & 1023) << 5;
    int t  = threadIdx.x;
    int dd   = t0 >> 12;
    int hh   = (t0 >> 10) & 3;
    int nsrc = (t0 & 1023) << 5;

    const float* sap = g_xsa + ((b*NHEAD + hh)*HDIM + dd)*NN + nsrc;
    for (int i = t; i < 1024; i += 128) sa[i >> 5][i & 31] = sap[i];
    for (int i = t; i < 1024; i += 128) {
        int c = i >> 5, ii = i & 31;
        ca[ii][c] = g_xca[(b*CC + c)*NN + t0 + ii];
    }
    for (int i = t; i < 1024; i += 128) {
        int ii = i >> 5, c = i & 31;
        xtl[ii][c] = g_xt[(b*NN + t0 + ii)*CC + c];
    }
    for (int i = t; i < 512; i += 128) {
        w1[i >> 5][i & 31] = o1w[i];
        w2[i >> 5][i & 31] = o2w[i];
    }
    if (t < 16) { b1[t] = o1b[t]; b2[t] = o2b[t]; }
    if (t < 32) gm[t] = gamma[t];
    __syncthreads();

    int ii = t & 31;
    int cg = t >> 5;
    #pragma unroll
    for (int cc = 0; cc < 8; cc++) {
        int c = cg*8 + cc;
        float val;
        if (c < 16) {
            float s = b1[c];
            #pragma unroll
            for (int k = 0; k < 32; k++) s += sa[ii][k]*w1[c][k];
            val = s;
        } else {
            int j = c - 16;
            float s = b2[j];
            #pragma unroll
            for (int k = 0; k < 32; k++) s += ca[ii][k]*w2[j][k];
            val = s;
        }
        float r = xtl[ii][c] + gm[c]*val;
        resm[ii][c] = r;
        g_skip[(b*CC + c)*NN + t0 + ii] = r;
    }
    __syncthreads();
    int tok = t >> 2, cgp = t & 3;
    int n   = t0 + tok;
    {
        float4 v0 = make_float4(resm[tok][cgp*8],   resm[tok][cgp*8+1],
                                resm[tok][cgp*8+2], resm[tok][cgp*8+3]);
        float4 v1 = make_float4(resm[tok][cgp*8+4], resm[tok][cgp*8+5],
                                resm[tok][cgp*8+6], resm[tok][cgp*8+7]);
        float4* d = reinterpret_cast<float4*>(g_skiptm + ((size_t)b*NN + n)*CC + cgp*8);
        d[0] = v0; d[1] = v1;
    }
    int npad = ((n >> 10) + 1)*1156 + (((n >> 5) & 31) + 1)*34 + (n & 31) + 1;
    uint32_t rw[8];
    #pragma unroll
    for (int c = 0; c < 8; c++) rw[c] = split_pack(resm[tok][cgp*8 + c]);
    float4* dst = reinterpret_cast<float4*>(
        g_pad1 + ((size_t)b*PADSTR + GUARD + npad)*64 + cgp*16);
    dst[0] = make_float4(__uint_as_float(rw[0]), __uint_as_float(rw[1]),
                         __uint_as_float(rw[2]), __uint_as_float(rw[3]));
    dst[1] = make_float4(__uint_as_float(rw[4]), __uint_as_float(rw[5]),
                         __uint_as_float(rw[6]), __uint_as_float(rw[7]));
}

// ---------------- weight prep: hi/lo bf16 images ----------------
__global__ __launch_bounds__(256) void kw_prep(const float* __restrict__ c1w,
                                               const float* __restrict__ c2w)
{
    int i = blockIdx.x*256 + threadIdx.x;      // 0 .. 2*27648
    if (i >= 2*27648) return;
    int which = (i >= 27648);
    int j = i - which*27648;                   // j = (co*32+ci)*27 + tap
    const float* w = which ? c2w : c1w;
    __nv_bfloat16* out = which ? g_wimg2 : g_wimg1;
    int tap = j % 27; int r = j / 27; int ci = r & 31; int co = r >> 5;
    float v = w[j];
    __nv_bfloat16 hi = __float2bfloat16_rn(v);
    __nv_bfloat16 lo = __float2bfloat16_rn(v - __bfloat162float(hi));
    __nv_bfloat16 z  = __float2bfloat16(0.f);
    out[((tap*2 + 0)*32 + co)*64 + 2*ci]     = hi;
    out[((tap*2 + 0)*32 + co)*64 + 2*ci + 1] = hi;
    out[((tap*2 + 1)*32 + co)*64 + 2*ci]     = lo;
    out[((tap*2 + 1)*32 + co)*64 + 2*ci + 1] = z;
}

// ---------------- conv via mma.sync v2: M=256, (kz,ky)-staged A with x-halo ----------------
// Per block: 256 consecutive padded tokens. 9 stages (kz,ky); each stages A rows
// [-1, 257) once and all 3 x-taps' weights; the 3 dx taps reuse the A stage with a
// row shift. 18 syncs/block, ~6x less LDG than v1.
// MODE 1: in=g_pad1 -> BN+lrelu -> g_pad2 (padded bf16 pairs)
// MODE 2: in=g_pad2 -> BN + skiptm residual + lrelu -> g_y2tm (fp32 [n][c])
#define CONV_ABYTES 33792          // 258 rows x 128B, rounded to 1KB
#define CONV_DSMEM  (CONV_ABYTES + 24576 + 1024)
template<int MODE>
__global__ __launch_bounds__(256) void conv_mma(
    const float* __restrict__ cb, const float* __restrict__ bg,
    const float* __restrict__ bb, const float* __restrict__ bm,
    const float* __restrict__ bv)
{
    extern __shared__ __align__(16) char dsm_raw[];
    __shared__ float scs[32], bss[32];

    const __nv_bfloat16* gA = (MODE == 1) ? g_pad1 : g_pad2;
    const __nv_bfloat16* gW = (MODE == 1) ? g_wimg1 : g_wimg2;

    int t = threadIdx.x, warp = t >> 5, lane = t & 31;
    int base = blockIdx.x * 256;
    int b    = blockIdx.y;
    long volr = (long)b*PADSTR + GUARD;

    uint32_t sbraw = smem_u32(dsm_raw);
    uint32_t sb    = (sbraw + 1023u) & ~1023u;
    char* dsm = dsm_raw + (sb - sbraw);
    uint32_t Abase = sb;
    uint32_t Bbase = sb + CONV_ABYTES;

    if (t < 32) {
        float a = bg[t]*rsqrtf(bv[t] + 1e-5f);
        scs[t] = a;
        bss[t] = (cb[t] - bm[t])*a + bb[t];
    }

    float acc[2][4][4];
    #pragma unroll
    for (int mt = 0; mt < 2; mt++)
        #pragma unroll
        for (int nb = 0; nb < 4; nb++)
            #pragma unroll
            for (int j = 0; j < 4; j++) acc[mt][nb][j] = 0.f;

    int a_rl = (lane & 7) + ((lane >> 3) & 1)*8;
    int a_cs = lane >> 4;
    int b_rn = (lane & 7) + ((lane >> 4) << 3);
    int b_cs = (lane >> 3) & 1;

    for (int kzy = 0; kzy < 9; kzy++) {
        int kz = kzy/3, ky = kzy - kz*3;
        __syncthreads();
        // ---- stage A: 258 rows (token -1 .. 256) for this (kz,ky) ----
        long rowb = volr + base + (kz - 1)*1156 + (ky - 1)*34 - 1;
        for (int idx = t; idx < 2064; idx += 256) {
            int r = idx >> 3, c16 = idx & 7;
            float4 v = *reinterpret_cast<const float4*>(gA + (rowb + r)*64 + c16*8);
            *reinterpret_cast<float4*>(dsm + SW128(r*128 + c16*16)) = v;
        }
        // ---- stage B: 3 x-taps x 2 chains x 32 n x 128B ----
        int tap0 = kzy*3;
        for (int idx = t; idx < 1536; idx += 256) {
            int row = idx >> 3, c16 = idx & 7;      // row = tapx*64 + chain*32 + n
            float4 v = *reinterpret_cast<const float4*>(
                gW + ((size_t)(tap0 + (row >> 6))*2 + ((row >> 5) & 1))*2048
                   + (row & 31)*64 + c16*8);
            *reinterpret_cast<float4*>(dsm + CONV_ABYTES + ((row >> 5) << 12)
                                       + SW128((row & 31)*128 + c16*16)) = v;
        }
        __syncthreads();
        // ---- compute: 3 dx x 4 ks ----
        #pragma unroll
        for (int dx = 0; dx < 3; dx++) {
            #pragma unroll
            for (int ks = 0; ks < 4; ks++) {
                uint32_t a[2][4];
                #pragma unroll
                for (int mt = 0; mt < 2; mt++) {
                    int row = warp*32 + mt*16 + a_rl + dx;
                    ldmx4(a[mt], Abase + SW128(row*128 + (2*ks + a_cs)*16));
                }
                uint32_t bf[2][8];
                #pragma unroll
                for (int chain = 0; chain < 2; chain++)
                    #pragma unroll
                    for (int np = 0; np < 2; np++) {
                        int rn = np*16 + b_rn;
                        ldmx4(&bf[chain][np*4],
                              Bbase + ((dx*2 + chain) << 12)
                              + SW128(rn*128 + (2*ks + b_cs)*16));
                    }
                #pragma unroll
                for (int mt = 0; mt < 2; mt++)
                    #pragma unroll
                    for (int nb = 0; nb < 4; nb++) {
                        int bi = (nb >> 1)*4 + (nb & 1)*2;
                        mma_bf16(acc[mt][nb], a[mt], bf[0][bi], bf[0][bi + 1]);
                        mma_bf16(acc[mt][nb], a[mt], bf[1][bi], bf[1][bi + 1]);
                    }
            }
        }
    }

    // ---- epilogue ----
    int cl = lane & 3;
    #pragma unroll
    for (int mt = 0; mt < 2; mt++)
        #pragma unroll
        for (int half = 0; half < 2; half++) {
            int m = base + warp*32 + mt*16 + (lane >> 2) + half*8;  // padded token
            int zp = m / 1156; int rem = m - zp*1156;
            int yp = rem / 34; int xp = rem - yp*34;
            if (zp < 1 || zp > 32 || yp < 1 || yp > 32 || xp < 1 || xp > 32) continue;
            if (MODE == 1) {
                __nv_bfloat16* dst = g_pad2 + (volr + m)*64;
                #pragma unroll
                for (int nb = 0; nb < 4; nb++) {
                    int co = nb*8 + 2*cl;
                    float v0 = acc[mt][nb][half*2]    *scs[co]   + bss[co];
                    float v1 = acc[mt][nb][half*2 + 1]*scs[co+1] + bss[co+1];
                    v0 = (v0 > 0.f) ? v0 : 0.01f*v0;
                    v1 = (v1 > 0.f) ? v1 : 0.01f*v1;
                    uint2 w2 = make_uint2(split_pack(v0), split_pack(v1));
                    *reinterpret_cast<uint2*>(dst + co*2) = w2;
                }
            } else {
                int n = (zp - 1)*1024 + (yp - 1)*32 + (xp - 1);
                const float* sk = g_skiptm + ((size_t)b*NN + n)*CC;
                float* dst = g_y2tm + ((size_t)b*NN + n)*CC;
                #pragma unroll
                for (int nb = 0; nb < 4; nb++) {
                    int co = nb*8 + 2*cl;
                    float2 s = *reinterpret_cast<const float2*>(sk + co);
                    float v0 = acc[mt][nb][half*2]    *scs[co]   + bss[co]   + s.x;
                    float v1 = acc[mt][nb][half*2 + 1]*scs[co+1] + bss[co+1] + s.y;
                    v0 = (v0 > 0.f) ? v0 : 0.01f*v0;
                    v1 = (v1 > 0.f) ? v1 : 0.01f*v1;
                    *reinterpret_cast<float2*>(dst + co) = make_float2(v0, v1);
                }
            }
        }
}

// ---------------- final: 1x1 conv residual (reads token-major y2) ----------------
__global__ __launch_bounds__(256) void k_final(
    const float* __restrict__ wp, const float* __restrict__ bp,
    float* __restrict__ outp)
{
    __shared__ float ys[64][33];
    __shared__ float wsm[32][32];
    __shared__ float bsh[32];
    int b  = blockIdx.x >> 9;
    int n0 = (blockIdx.x & 511) << 6;
    int t  = threadIdx.x;
    for (int i = t; i < 2048; i += 256) {
        int nn = i >> 5, ci = i & 31;
        ys[nn][ci] = g_y2tm[((size_t)b*NN + n0 + nn)*CC + ci];
    }
    for (int i = t; i < 1024; i += 256) wsm[i >> 5][i & 31] = wp[i];
    if (t < 32) bsh[t] = bp[t];
    __syncthreads();
    int nn = t & 63;
    int cg = t >> 6;
    #pragma unroll
    for (int cc = 0; cc < 8; cc++) {
        int co = cg*8 + cc;
        float s = bsh[co];
        #pragma unroll
        for (int ci = 0; ci < 32; ci++) s += wsm[co][ci]*ys[nn][ci];
        int idx = (b*32 + co)*NN + n0 + nn;
        outp[idx] = g_skip[idx] + s;
    }
}

// ---------------- launch ----------------
extern "C" void kernel_launch(void* const* d_in, const int* in_sizes, int n_in,
                              void* d_out, int out_size)
{
    const float* x    = (const float*)d_in[0];
    const float* pos  = (const float*)d_in[1];
    const float* lng  = (const float*)d_in[2];
    const float* lnb  = (const float*)d_in[3];
    const float* gam  = (const float*)d_in[4];
    const float* Wq   = (const float*)d_in[5];
    const float* EFw  = (const float*)d_in[6];
    const float* EFb  = (const float*)d_in[7];
    const float* t1   = (const float*)d_in[8];
    const float* t2   = (const float*)d_in[9];
    const float* o1w  = (const float*)d_in[10];
    const float* o1b  = (const float*)d_in[11];
    const float* o2w  = (const float*)d_in[12];
    const float* o2b  = (const float*)d_in[13];
    const float* c1w  = (const float*)d_in[14];
    const float* c1b  = (const float*)d_in[15];
    const float* b1g  = (const float*)d_in[16];
    const float* b1b  = (const float*)d_in[17];
    const float* b1m  = (const float*)d_in[18];
    const float* b1v  = (const float*)d_in[19];
    const float* c2w  = (const float*)d_in[20];
    const float* c2b  = (const float*)d_in[21];
    const float* b2g  = (const float*)d_in[22];
    const float* b2b  = (const float*)d_in[23];
    const float* b2m  = (const float*)d_in[24];
    const float* b2v  = (const float*)d_in[25];
    const float* cpw  = (const float*)d_in[26];
    const float* cpb  = (const float*)d_in[27];
    float* outp = (float*)d_out;

    static int attr_done = 0;
    if (!attr_done) {
        cudaFuncSetAttribute(conv_mma<1>, cudaFuncAttributeMaxDynamicSharedMemorySize, CONV_DSMEM);
        cudaFuncSetAttribute(conv_mma<2>, cudaFuncAttributeMaxDynamicSharedMemorySize, CONV_DSMEM);
        attr_done = 1;
    }

    kw_prep<<<216, 256>>>(c1w, c2w);
    k1_tok_ln_qkvv<<<4096, 256>>>(x, pos, lng, lnb, Wq);
    k2_proj_partial<<<dim3(64, 4), 128>>>(EFw);
    k2_proj_reduce<<<64, 256>>>(EFb);
    k3a_gram_partial<<<dim3(8, 16), 256>>>();
    k3a_finalize<<<16, 128>>>(t1);
    k3b_attn<<<dim3(256, 16), 128>>>(t2);
    k4_combine<<<4096, 128>>>(o1w, o1b, o2w, o2b, gam);
    conv_mma<1><<<dim3(NTILE2, BB), 256, CONV_DSMEM>>>(c1b, b1g, b1b, b1m, b1v);
    conv_mma<2><<<dim3(NTILE2, BB), 256, CONV_DSMEM>>>(c2b, b2g, b2b, b2m, b2v);
    k_final<<<2048, 256>>>(cpw, cpb, outp);
}

// round 13
// speedup vs baseline: 2.3340x; 1.3196x over previous
#include <cuda_runtime.h>
#include <cuda_fp16.h>
#include <math.h>
#include <stdint.h>

#define BB 4
#define CC 32
#define NHEAD 4
#define HDIM 8
#define NN 32768
#define PP 64

#define PADN   39304            // 34*34*34
#define GUARD  1536
#define PADSTR (PADN + 2*GUARD) // rows per batch
#define NTILE2 146              // tokens [1024, 38400) in 256-token blocks

// ---------------- scratch (static device memory; no allocations) ----------------
static __device__ float g_xt  [BB*NN*CC];
static __device__ float g_q   [BB*CC*NN];
static __device__ float g_k   [BB*CC*NN];
static __device__ float g_vca [BB*CC*NN];
static __device__ float g_vsa [BB*CC*NN];
static __device__ float g_part[64*256*PP];
static __device__ float g_kproj[BB*CC*PP];
static __device__ float g_vproj[BB*CC*PP];
static __device__ float g_npart[8*16*80];
static __device__ float g_qinv[BB*CC];
static __device__ float g_attnca[BB*NHEAD*HDIM*HDIM];
static __device__ float g_xsa [BB*CC*NN];
static __device__ float g_xca [BB*CC*NN];
static __device__ float g_skip[BB*CC*NN];      // [b][c][n] for k_final
static __device__ float g_skiptm[BB*NN*CC];    // [b][n][c] for conv2 residual
static __device__ float g_y2tm [BB*NN*CC];     // [b][n][c] conv2 output
// padded token-major conv activations: [b][padtoken][32 fp16]
// zero-initialized; halo/guard rows are NEVER written -> stay zero on every replay.
static __device__ __align__(16) __half g_pad1[(size_t)BB*PADSTR*32];
static __device__ __align__(16) __half g_pad2[(size_t)BB*PADSTR*32];
// weight images: [tap][co(32)][ci(32)] fp16
static __device__ __align__(16) __half g_wimg1[27*32*32];
static __device__ __align__(16) __half g_wimg2[27*32*32];

// ---------------- helpers ----------------
#define SW64(o) ((o) ^ (((o) >> 3) & 0x30))

__device__ __forceinline__ uint32_t smem_u32(const void* p) {
    uint32_t a;
    asm("{ .reg .u64 t; cvta.to.shared.u64 t, %1; cvt.u32.u64 %0, t; }" : "=r"(a) : "l"(p));
    return a;
}
__device__ __forceinline__ void ldmx4(uint32_t* r, uint32_t addr) {
    asm volatile("ldmatrix.sync.aligned.m8n8.x4.shared.b16 {%0,%1,%2,%3}, [%4];"
                 : "=r"(r[0]), "=r"(r[1]), "=r"(r[2]), "=r"(r[3]) : "r"(addr));
}
__device__ __forceinline__ void mma_fp16(float* d, const uint32_t* a, uint32_t b0, uint32_t b1) {
    asm volatile("mma.sync.aligned.m16n8k16.row.col.f32.f16.f16.f32 "
                 "{%0,%1,%2,%3}, {%4,%5,%6,%7}, {%8,%9}, {%0,%1,%2,%3};"
                 : "+f"(d[0]), "+f"(d[1]), "+f"(d[2]), "+f"(d[3])
                 : "r"(a[0]), "r"(a[1]), "r"(a[2]), "r"(a[3]), "r"(b0), "r"(b1));
}

// ---------------- K1: transpose+pos, layernorm, QKVV GEMM ----------------
__global__ __launch_bounds__(256) void k1_tok_ln_qkvv(
    const float* __restrict__ x, const float* __restrict__ pos,
    const float* __restrict__ lng, const float* __restrict__ lnb,
    const float* __restrict__ Wq)
{
    __shared__ float xts[32][33];
    __shared__ float Ws[32][128];
    int b  = blockIdx.x >> 10;
    int n0 = (blockIdx.x & 1023) << 5;
    int t  = threadIdx.x;

    for (int i = t; i < 32*128; i += 256) Ws[i >> 7][i & 127] = Wq[i];
    for (int i = t; i < 1024; i += 256) {
        int j = i & 31, c = i >> 5;
        xts[j][c] = x[(b*CC + c)*NN + n0 + j];
    }
    __syncthreads();
    for (int i = t; i < 1024; i += 256) {
        int c = i & 31, j = i >> 5;
        float v = xts[j][c] + pos[(n0 + j)*CC + c];
        xts[j][c] = v;
        g_xt[(b*NN + n0 + j)*CC + c] = v;
    }
    __syncthreads();
    int w = t >> 5, lane = t & 31;
    for (int jj = 0; jj < 4; jj++) {
        int j = w*4 + jj;
        float v = xts[j][lane];
        float s = v, ss = v*v;
        #pragma unroll
        for (int o = 16; o > 0; o >>= 1) {
            s  += __shfl_xor_sync(0xffffffffu, s, o);
            ss += __shfl_xor_sync(0xffffffffu, ss, o);
        }
        float mu  = s * (1.0f/32.0f);
        float var = ss * (1.0f/32.0f) - mu*mu;
        float r   = rsqrtf(var + 1e-5f);
        xts[j][lane] = (v - mu) * r * lng[lane] + lnb[lane];
    }
    __syncthreads();
    float acc[16];
    #pragma unroll
    for (int i = 0; i < 16; i++) acc[i] = 0.f;
    int c0 = w * 16;
    #pragma unroll
    for (int kk = 0; kk < 32; kk++) {
        float xv = xts[lane][kk];
        #pragma unroll
        for (int i = 0; i < 16; i++) acc[i] += xv * Ws[kk][c0 + i];
    }
    #pragma unroll
    for (int i = 0; i < 16; i++) {
        int col   = c0 + i;
        int which = col >> 5;
        int ch    = col & 31;
        float* dst = (which == 0) ? g_q : (which == 1) ? g_k :
                     (which == 2) ? g_vca : g_vsa;
        dst[(b*CC + ch)*NN + n0 + lane] = acc[i];
    }
}

// ---------------- K2: EF projections ----------------
__global__ __launch_bounds__(128) void k2_proj_partial(const float* __restrict__ EFw)
{
    __shared__ __align__(16) float Ks[64][68];
    __shared__ __align__(16) float Es[64][68];
    int chunk = blockIdx.x;
    int rg    = blockIdx.y;
    int t     = threadIdx.x;
    const float* src = (rg < 2) ? g_k : g_vsa;
    int r0  = (rg & 1) * 64;
    int nb0 = chunk * 512;

    float acc[4][8];
    #pragma unroll
    for (int i = 0; i < 4; i++)
        #pragma unroll
        for (int j = 0; j < 8; j++) acc[i][j] = 0.f;

    int pb = (t & 7) * 8;
    int ro = (t >> 3) * 4;
    for (int st = 0; st < 8; st++) {
        int nb = nb0 + st*64;
        __syncthreads();
        for (int i = t; i < 64*64; i += 128) {
            int nn = i & 63, rr = i >> 6;
            Ks[rr][nn] = src[(r0 + rr)*NN + nb + nn];
            Es[rr][nn] = EFw[rr*NN + nb + nn];
        }
        __syncthreads();
        #pragma unroll 4
        for (int nn = 0; nn < 64; nn += 4) {
            float4 rv[4];
            #pragma unroll
            for (int i = 0; i < 4; i++)
                rv[i] = *reinterpret_cast<const float4*>(&Ks[ro + i][nn]);
            #pragma unroll
            for (int j = 0; j < 8; j++) {
                float4 e = *reinterpret_cast<const float4*>(&Es[pb + j][nn]);
                #pragma unroll
                for (int i = 0; i < 4; i++) {
                    acc[i][j] += rv[i].x*e.x + rv[i].y*e.y
                               + rv[i].z*e.z + rv[i].w*e.w;
                }
            }
        }
    }
    #pragma unroll
    for (int i = 0; i < 4; i++)
        #pragma unroll
        for (int j = 0; j < 8; j++)
            g_part[(chunk*256 + rg*64 + ro + i)*PP + pb + j] = acc[i][j];
}

__global__ __launch_bounds__(256) void k2_proj_reduce(const float* __restrict__ EFb)
{
    int idx = blockIdx.x * 256 + threadIdx.x;
    int row = idx >> 6, p = idx & 63;
    float s = 0.f;
    for (int c = 0; c < 64; c++) s += g_part[(c*256 + row)*PP + p];
    s += EFb[p];
    if (row < 128) g_kproj[row*PP + p] = s;
    else           g_vproj[(row - 128)*PP + p] = s;
}

// ---------------- K3a: gram matrix + L2 norms ----------------
__global__ __launch_bounds__(256) void k3a_gram_partial()
{
    int split = blockIdx.x;
    int bh    = blockIdx.y;
    int t     = threadIdx.x;
    const float* qb = g_q + bh*8*NN;
    const float* kb = g_k + bh*8*NN;

    float v[80];
    #pragma unroll
    for (int i = 0; i < 80; i++) v[i] = 0.f;

    int nend = split*4096 + 4096;
    for (int n = split*4096 + t; n < nend; n += 256) {
        float qv[8], kv[8];
        #pragma unroll
        for (int d = 0; d < 8; d++) { qv[d] = qb[d*NN + n]; kv[d] = kb[d*NN + n]; }
        #pragma unroll
        for (int d = 0; d < 8; d++) {
            v[64 + d] += qv[d]*qv[d];
            v[72 + d] += kv[d]*kv[d];
            #pragma unroll
            for (int e = 0; e < 8; e++) v[d*8 + e] += qv[d]*kv[e];
        }
    }
    __shared__ float wsum[8][80];
    int w = t >> 5, lane = t & 31;
    #pragma unroll
    for (int i = 0; i < 80; i++) {
        float s = v[i];
        #pragma unroll
        for (int o = 16; o > 0; o >>= 1) s += __shfl_xor_sync(0xffffffffu, s, o);
        if (lane == 0) wsum[w][i] = s;
    }
    __syncthreads();
    if (t < 80) {
        float s = 0.f;
        #pragma unroll
        for (int ww = 0; ww < 8; ww++) s += wsum[ww][t];
        g_npart[(split*16 + bh)*80 + t] = s;
    }
}

__global__ __launch_bounds__(128) void k3a_finalize(const float* __restrict__ temp1)
{
    int bh = blockIdx.x;
    int t  = threadIdx.x;
    __shared__ float tot[80];
    __shared__ float qi[8], ki[8];
    if (t < 80) {
        float s = 0.f;
        #pragma unroll
        for (int sp = 0; sp < 8; sp++) s += g_npart[(sp*16 + bh)*80 + t];
        tot[t] = s;
    }
    __syncthreads();
    if (t < 8) {
        float qn = sqrtf(tot[64 + t]);
        float kn = sqrtf(tot[72 + t]);
        qi[t] = 1.0f / fmaxf(qn, 1e-12f);
        ki[t] = 1.0f / fmaxf(kn, 1e-12f);
        g_qinv[bh*8 + t] = qi[t];
    }
    __syncthreads();
    if (t < 8) {
        int h = bh & 3;
        float t1 = temp1[h];
        float sc[8];
        float m = -1e30f;
        #pragma unroll
        for (int e = 0; e < 8; e++) {
            sc[e] = tot[t*8 + e] * qi[t] * ki[e] * t1;
            m = fmaxf(m, sc[e]);
        }
        float sum = 0.f;
        #pragma unroll
        for (int e = 0; e < 8; e++) { sc[e] = __expf(sc[e] - m); sum += sc[e]; }
        float inv = 1.0f / sum;
        #pragma unroll
        for (int e = 0; e < 8; e++) g_attnca[bh*64 + t*8 + e] = sc[e]*inv;
    }
}

// ---------------- K3b ----------------
__global__ __launch_bounds__(128) void k3b_attn(const float* __restrict__ temp2)
{
    int bh = blockIdx.y;
    int n  = blockIdx.x * 128 + threadIdx.x;
    int h  = bh & 3;
    int t  = threadIdx.x;
    __shared__ float kq[8][64], vp[8][64], A[8][8];
    float t2 = temp2[h];
    for (int i = t; i < 512; i += 128) {
        int d = i >> 6, p = i & 63;
        kq[d][p] = g_qinv[bh*8 + d] * g_kproj[(bh*8 + d)*PP + p] * t2;
        vp[d][p] = g_vproj[(bh*8 + d)*PP + p];
    }
    if (t < 64) A[t >> 3][t & 7] = g_attnca[bh*64 + t];
    __syncthreads();

    int base = bh*8*NN + n;
    float qv[8];
    #pragma unroll
    for (int d = 0; d < 8; d++) qv[d] = g_q[base + d*NN];

    float s[64];
    #pragma unroll
    for (int p = 0; p < 64; p++) s[p] = qv[0]*kq[0][p];
    #pragma unroll
    for (int d = 1; d < 8; d++)
        #pragma unroll
        for (int p = 0; p < 64; p++) s[p] += qv[d]*kq[d][p];

    float m = s[0];
    #pragma unroll
    for (int p = 1; p < 64; p++) m = fmaxf(m, s[p]);
    float sum = 0.f;
    #pragma unroll
    for (int p = 0; p < 64; p++) { s[p] = __expf(s[p] - m); sum += s[p]; }
    float inv = 1.0f / sum;

    #pragma unroll
    for (int d = 0; d < 8; d++) {
        float o = 0.f;
        #pragma unroll
        for (int p = 0; p < 64; p++) o += s[p]*vp[d][p];
        g_xsa[base + d*NN] = o * inv;
    }
    float vv[8];
    #pragma unroll
    for (int e = 0; e < 8; e++) vv[e] = g_vca[base + e*NN];
    #pragma unroll
    for (int d = 0; d < 8; d++) {
        float xc = 0.f;
        #pragma unroll
        for (int e = 0; e < 8; e++) xc += A[d][e]*vv[e];
        g_xca[base + d*NN] = xc;
    }
}

// ---------------- K4: combine; write skip ([c][n] and [n][c]) + pad1 (fp16) ----------------
__global__ __launch_bounds__(128) void k4_combine(
    const float* __restrict__ o1w, const float* __restrict__ o1b,
    const float* __restrict__ o2w, const float* __restrict__ o2b,
    const float* __restrict__ gamma)
{
    __shared__ float sa[32][33], ca[32][33], xtl[32][33], resm[32][33];
    __shared__ float w1[16][32], w2[16][32], b1[16], b2[16], gm[32];
    int b  = blockIdx.x >> 10;
    int t0 = (blockIdx.x & 1023) << 5;
    int t  = threadIdx.x;
    int dd   = t0 >> 12;
    int hh   = (t0 >> 10) & 3;
    int nsrc = (t0 & 1023) << 5;

    const float* sap = g_xsa + ((b*NHEAD + hh)*HDIM + dd)*NN + nsrc;
    for (int i = t; i < 1024; i += 128) sa[i >> 5][i & 31] = sap[i];
    for (int i = t; i < 1024; i += 128) {
        int c = i >> 5, ii = i & 31;
        ca[ii][c] = g_xca[(b*CC + c)*NN + t0 + ii];
    }
    for (int i = t; i < 1024; i += 128) {
        int ii = i >> 5, c = i & 31;
        xtl[ii][c] = g_xt[(b*NN + t0 + ii)*CC + c];
    }
    for (int i = t; i < 512; i += 128) {
        w1[i >> 5][i & 31] = o1w[i];
        w2[i >> 5][i & 31] = o2w[i];
    }
    if (t < 16) { b1[t] = o1b[t]; b2[t] = o2b[t]; }
    if (t < 32) gm[t] = gamma[t];
    __syncthreads();

    int ii = t & 31;
    int cg = t >> 5;
    #pragma unroll
    for (int cc = 0; cc < 8; cc++) {
        int c = cg*8 + cc;
        float val;
        if (c < 16) {
            float s = b1[c];
            #pragma unroll
            for (int k = 0; k < 32; k++) s += sa[ii][k]*w1[c][k];
            val = s;
        } else {
            int j = c - 16;
            float s = b2[j];
            #pragma unroll
            for (int k = 0; k < 32; k++) s += ca[ii][k]*w2[j][k];
            val = s;
        }
        float r = xtl[ii][c] + gm[c]*val;
        resm[ii][c] = r;
        g_skip[(b*CC + c)*NN + t0 + ii] = r;
    }
    __syncthreads();
    int tok = t >> 2, cgp = t & 3;
    int n   = t0 + tok;
    {
        float4 v0 = make_float4(resm[tok][cgp*8],   resm[tok][cgp*8+1],
                                resm[tok][cgp*8+2], resm[tok][cgp*8+3]);
        float4 v1 = make_float4(resm[tok][cgp*8+4], resm[tok][cgp*8+5],
                                resm[tok][cgp*8+6], resm[tok][cgp*8+7]);
        float4* d = reinterpret_cast<float4*>(g_skiptm + ((size_t)b*NN + n)*CC + cgp*8);
        d[0] = v0; d[1] = v1;
    }
    // pad1 fp16: 8 halfs = 16B per thread
    int npad = ((n >> 10) + 1)*1156 + (((n >> 5) & 31) + 1)*34 + (n & 31) + 1;
    __half2 h[4];
    #pragma unroll
    for (int j = 0; j < 4; j++)
        h[j] = __half2(__float2half_rn(resm[tok][cgp*8 + 2*j]),
                       __float2half_rn(resm[tok][cgp*8 + 2*j + 1]));
    *reinterpret_cast<uint4*>(g_pad1 + ((size_t)b*PADSTR + GUARD + npad)*32 + cgp*8) =
        *reinterpret_cast<uint4*>(h);
}

// ---------------- weight prep: fp16 images [tap][co][ci] ----------------
__global__ __launch_bounds__(256) void kw_prep(const float* __restrict__ c1w,
                                               const float* __restrict__ c2w)
{
    int i = blockIdx.x*256 + threadIdx.x;      // 0 .. 2*27648
    if (i >= 2*27648) return;
    int which = (i >= 27648);
    int j = i - which*27648;                   // j = (co*32+ci)*27 + tap
    const float* w = which ? c2w : c1w;
    __half* out = which ? g_wimg2 : g_wimg1;
    int tap = j % 27; int r = j / 27; int ci = r & 31; int co = r >> 5;
    out[(tap*32 + co)*32 + ci] = __float2half_rn(w[j]);
}

// ---------------- conv via mma.sync v3: single-chain fp16, K=32, 64B rows ----------------
// Per block: 256 padded tokens in [1024, 38400). 9 (kz,ky) stages; A staged once with
// x-halo (258 rows x 64B, SW64); 3 dx taps reuse with row shift. K=32 -> 2 mma K-steps.
// MODE 1: in=g_pad1 -> BN+lrelu -> g_pad2 (fp16)
// MODE 2: in=g_pad2 -> BN + skiptm residual + lrelu -> g_y2tm (fp32 [n][c])
template<int MODE>
__global__ __launch_bounds__(256) void conv_mma(
    const float* __restrict__ cb, const float* __restrict__ bg,
    const float* __restrict__ bb, const float* __restrict__ bm,
    const float* __restrict__ bv)
{
    __shared__ __align__(128) __half Asm[258*32];   // 16.5 KB
    __shared__ __align__(128) __half Bsm[3*32*32];  // 6 KB
    __shared__ float scs[32], bss[32];

    const __half* gA = (MODE == 1) ? g_pad1 : g_pad2;
    const __half* gW = (MODE == 1) ? g_wimg1 : g_wimg2;

    int t = threadIdx.x, warp = t >> 5, lane = t & 31;
    int base = 1024 + blockIdx.x * 256;
    int b    = blockIdx.y;
    long volr = (long)b*PADSTR + GUARD;

    if (t < 32) {
        float a = bg[t]*rsqrtf(bv[t] + 1e-5f);
        scs[t] = a;
        bss[t] = (cb[t] - bm[t])*a + bb[t];
    }

    uint32_t Abase = smem_u32(Asm), Bbase = smem_u32(Bsm);
    float acc[2][4][4];
    #pragma unroll
    for (int mt = 0; mt < 2; mt++)
        #pragma unroll
        for (int nb = 0; nb < 4; nb++)
            #pragma unroll
            for (int j = 0; j < 4; j++) acc[mt][nb][j] = 0.f;

    int a_rl = (lane & 7) + ((lane >> 3) & 1)*8;
    int a_cs = lane >> 4;
    int b_rn = (lane & 7) + ((lane >> 4) << 3);
    int b_cs = (lane >> 3) & 1;

    for (int kzy = 0; kzy < 9; kzy++) {
        int kz = kzy/3, ky = kzy - kz*3;
        __syncthreads();
        // ---- stage A: 258 rows x 64B for this (kz,ky), SW64 ----
        long rowb = volr + base + (kz - 1)*1156 + (ky - 1)*34 - 1;
        for (int idx = t; idx < 1032; idx += 256) {
            int r = idx >> 2, c = idx & 3;
            float4 v = *reinterpret_cast<const float4*>(gA + (rowb + r)*32 + c*8);
            *reinterpret_cast<float4*>(
                reinterpret_cast<char*>(Asm) + SW64(r*64 + c*16)) = v;
        }
        // ---- stage B: 3 dx x 32 co x 64B ----
        for (int idx = t; idx < 384; idx += 256) {
            int row = idx >> 2, c = idx & 3;      // row = dx*32 + co
            int dx = row >> 5, co = row & 31;
            float4 v = *reinterpret_cast<const float4*>(
                gW + ((size_t)(kzy*3 + dx)*32 + co)*32 + c*8);
            *reinterpret_cast<float4*>(
                reinterpret_cast<char*>(Bsm) + dx*2048 + SW64(co*64 + c*16)) = v;
        }
        __syncthreads();
        // ---- compute: 3 dx x 2 ks ----
        #pragma unroll
        for (int dx = 0; dx < 3; dx++) {
            #pragma unroll
            for (int ks = 0; ks < 2; ks++) {
                uint32_t a[2][4];
                #pragma unroll
                for (int mt = 0; mt < 2; mt++) {
                    int row = warp*32 + mt*16 + a_rl + dx;
                    ldmx4(a[mt], Abase + SW64(row*64 + (2*ks + a_cs)*16));
                }
                uint32_t bf[8];
                #pragma unroll
                for (int np = 0; np < 2; np++) {
                    int rn = np*16 + b_rn;
                    ldmx4(&bf[np*4],
                          Bbase + dx*2048 + SW64(rn*64 + (2*ks + b_cs)*16));
                }
                #pragma unroll
                for (int mt = 0; mt < 2; mt++)
                    #pragma unroll
                    for (int nb = 0; nb < 4; nb++) {
                        int bi = (nb >> 1)*4 + (nb & 1)*2;
                        mma_fp16(acc[mt][nb], a[mt], bf[bi], bf[bi + 1]);
                    }
            }
        }
    }

    // ---- epilogue ----
    int cl = lane & 3;
    #pragma unroll
    for (int mt = 0; mt < 2; mt++)
        #pragma unroll
        for (int half = 0; half < 2; half++) {
            int m = base + warp*32 + mt*16 + (lane >> 2) + half*8;  // padded token
            int zp = m / 1156; int rem = m - zp*1156;
            int yp = rem / 34; int xp = rem - yp*34;
            if (zp < 1 || zp > 32 || yp < 1 || yp > 32 || xp < 1 || xp > 32) continue;
            if (MODE == 1) {
                __half* dst = g_pad2 + (volr + m)*32;
                #pragma unroll
                for (int nb = 0; nb < 4; nb++) {
                    int co = nb*8 + 2*cl;
                    float v0 = acc[mt][nb][half*2]    *scs[co]   + bss[co];
                    float v1 = acc[mt][nb][half*2 + 1]*scs[co+1] + bss[co+1];
                    v0 = (v0 > 0.f) ? v0 : 0.01f*v0;
                    v1 = (v1 > 0.f) ? v1 : 0.01f*v1;
                    *reinterpret_cast<__half2*>(dst + co) =
                        __half2(__float2half_rn(v0), __float2half_rn(v1));
                }
            } else {
                int n = (zp - 1)*1024 + (yp - 1)*32 + (xp - 1);
                const float* sk = g_skiptm + ((size_t)b*NN + n)*CC;
                float* dst = g_y2tm + ((size_t)b*NN + n)*CC;
                #pragma unroll
                for (int nb = 0; nb < 4; nb++) {
                    int co = nb*8 + 2*cl;
                    float2 s = *reinterpret_cast<const float2*>(sk + co);
                    float v0 = acc[mt][nb][half*2]    *scs[co]   + bss[co]   + s.x;
                    float v1 = acc[mt][nb][half*2 + 1]*scs[co+1] + bss[co+1] + s.y;
                    v0 = (v0 > 0.f) ? v0 : 0.01f*v0;
                    v1 = (v1 > 0.f) ? v1 : 0.01f*v1;
                    *reinterpret_cast<float2*>(dst + co) = make_float2(v0, v1);
                }
            }
        }
}

// ---------------- final: 1x1 conv residual (reads token-major y2) ----------------
__global__ __launch_bounds__(256) void k_final(
    const float* __restrict__ wp, const float* __restrict__ bp,
    float* __restrict__ outp)
{
    __shared__ float ys[64][33];
    __shared__ float wsm[32][32];
    __shared__ float bsh[32];
    int b  = blockIdx.x >> 9;
    int n0 = (blockIdx.x & 511) << 6;
    int t  = threadIdx.x;
    for (int i = t; i < 2048; i += 256) {
        int nn = i >> 5, ci = i & 31;
        ys[nn][ci] = g_y2tm[((size_t)b*NN + n0 + nn)*CC + ci];
    }
    for (int i = t; i < 1024; i += 256) wsm[i >> 5][i & 31] = wp[i];
    if (t < 32) bsh[t] = bp[t];
    __syncthreads();
    int nn = t & 63;
    int cg = t >> 6;
    #pragma unroll
    for (int cc = 0; cc < 8; cc++) {
        int co = cg*8 + cc;
        float s = bsh[co];
        #pragma unroll
        for (int ci = 0; ci < 32; ci++) s += wsm[co][ci]*ys[nn][ci];
        int idx = (b*32 + co)*NN + n0 + nn;
        outp[idx] = g_skip[idx] + s;
    }
}

// ---------------- launch ----------------
extern "C" void kernel_launch(void* const* d_in, const int* in_sizes, int n_in,
                              void* d_out, int out_size)
{
    const float* x    = (const float*)d_in[0];
    const float* pos  = (const float*)d_in[1];
    const float* lng  = (const float*)d_in[2];
    const float* lnb  = (const float*)d_in[3];
    const float* gam  = (const float*)d_in[4];
    const float* Wq   = (const float*)d_in[5];
    const float* EFw  = (const float*)d_in[6];
    const float* EFb  = (const float*)d_in[7];
    const float* t1   = (const float*)d_in[8];
    const float* t2   = (const float*)d_in[9];
    const float* o1w  = (const float*)d_in[10];
    const float* o1b  = (const float*)d_in[11];
    const float* o2w  = (const float*)d_in[12];
    const float* o2b  = (const float*)d_in[13];
    const float* c1w  = (const float*)d_in[14];
    const float* c1b  = (const float*)d_in[15];
    const float* b1g  = (const float*)d_in[16];
    const float* b1b  = (const float*)d_in[17];
    const float* b1m  = (const float*)d_in[18];
    const float* b1v  = (const float*)d_in[19];
    const float* c2w  = (const float*)d_in[20];
    const float* c2b  = (const float*)d_in[21];
    const float* b2g  = (const float*)d_in[22];
    const float* b2b  = (const float*)d_in[23];
    const float* b2m  = (const float*)d_in[24];
    const float* b2v  = (const float*)d_in[25];
    const float* cpw  = (const float*)d_in[26];
    const float* cpb  = (const float*)d_in[27];
    float* outp = (float*)d_out;

    // order chosen so the profiler's fixed capture slot (launch index 3) lands on
    // k2_proj_partial; all data dependencies preserved.
    k1_tok_ln_qkvv<<<4096, 256>>>(x, pos, lng, lnb, Wq);          // 0
    k3a_gram_partial<<<dim3(8, 16), 256>>>();                      // 1
    k3a_finalize<<<16, 128>>>(t1);                                 // 2
    k2_proj_partial<<<dim3(64, 4), 128>>>(EFw);                    // 3  <- profiled
    k2_proj_reduce<<<64, 256>>>(EFb);                              // 4
    kw_prep<<<216, 256>>>(c1w, c2w);                               // 5
    k3b_attn<<<dim3(256, 16), 128>>>(t2);                          // 6
    k4_combine<<<4096, 128>>>(o1w, o1b, o2w, o2b, gam);            // 7
    conv_mma<1><<<dim3(NTILE2, BB), 256>>>(c1b, b1g, b1b, b1m, b1v);
    conv_mma<2><<<dim3(NTILE2, BB), 256>>>(c2b, b2g, b2b, b2m, b2v);
    k_final<<<2048, 256>>>(cpw, cpb, outp);
}

// round 14
// speedup vs baseline: 3.2586x; 1.3962x over previous
#include <cuda_runtime.h>
#include <cuda_fp16.h>
#include <math.h>
#include <stdint.h>

#define BB 4
#define CC 32
#define NHEAD 4
#define HDIM 8
#define NN 32768
#define PP 64
#define KSPLIT 128

#define PADN   39304            // 34*34*34
#define GUARD  1536
#define PADSTR (PADN + 2*GUARD) // rows per batch
#define NTILE2 146              // tokens [1024, 38400) in 256-token blocks

// ---------------- scratch (static device memory; no allocations) ----------------
static __device__ float g_xt  [BB*NN*CC];
static __device__ float g_q   [BB*CC*NN];
static __device__ float g_k   [BB*CC*NN];
static __device__ float g_vca [BB*CC*NN];
static __device__ float g_vsa [BB*CC*NN];
static __device__ float g_part[(size_t)KSPLIT*256*64];   // split-K partials
static __device__ float g_kproj[BB*CC*PP];
static __device__ float g_vproj[BB*CC*PP];
static __device__ float g_npart[8*16*80];
static __device__ float g_qinv[BB*CC];
static __device__ float g_attnca[BB*NHEAD*HDIM*HDIM];
static __device__ float g_xsa [BB*CC*NN];
static __device__ float g_xca [BB*CC*NN];
static __device__ float g_skip[BB*CC*NN];      // [b][c][n] for k_final
static __device__ float g_skiptm[BB*NN*CC];    // [b][n][c] for conv2 residual
static __device__ float g_y2tm [BB*NN*CC];     // [b][n][c] conv2 output
// fp16 images for the EF projection GEMM: rows 0-127 = k (b*32+c), 128-255 = v_sa
static __device__ __align__(16) __half g_kv16[(size_t)256*NN];
static __device__ __align__(16) __half g_ef16[(size_t)PP*NN];
// padded token-major conv activations: [b][padtoken][32 fp16]
static __device__ __align__(16) __half g_pad1[(size_t)BB*PADSTR*32];
static __device__ __align__(16) __half g_pad2[(size_t)BB*PADSTR*32];
// weight images: [tap][co(32)][ci(32)] fp16
static __device__ __align__(16) __half g_wimg1[27*32*32];
static __device__ __align__(16) __half g_wimg2[27*32*32];

// ---------------- helpers ----------------
#define SW64(o)  ((o) ^ (((o) >> 3) & 0x30))
#define SW128(o) ((o) ^ (((o) >> 3) & 0x70))

__device__ __forceinline__ uint32_t smem_u32(const void* p) {
    uint32_t a;
    asm("{ .reg .u64 t; cvta.to.shared.u64 t, %1; cvt.u32.u64 %0, t; }" : "=r"(a) : "l"(p));
    return a;
}
__device__ __forceinline__ void ldmx4(uint32_t* r, uint32_t addr) {
    asm volatile("ldmatrix.sync.aligned.m8n8.x4.shared.b16 {%0,%1,%2,%3}, [%4];"
                 : "=r"(r[0]), "=r"(r[1]), "=r"(r[2]), "=r"(r[3]) : "r"(addr));
}
__device__ __forceinline__ void mma_fp16(float* d, const uint32_t* a, uint32_t b0, uint32_t b1) {
    asm volatile("mma.sync.aligned.m16n8k16.row.col.f32.f16.f16.f32 "
                 "{%0,%1,%2,%3}, {%4,%5,%6,%7}, {%8,%9}, {%0,%1,%2,%3};"
                 : "+f"(d[0]), "+f"(d[1]), "+f"(d[2]), "+f"(d[3])
                 : "r"(a[0]), "r"(a[1]), "r"(a[2]), "r"(a[3]), "r"(b0), "r"(b1));
}

// ---------------- K1: transpose+pos, layernorm, QKVV GEMM (+fp16 k/v images) ----------------
__global__ __launch_bounds__(256) void k1_tok_ln_qkvv(
    const float* __restrict__ x, const float* __restrict__ pos,
    const float* __restrict__ lng, const float* __restrict__ lnb,
    const float* __restrict__ Wq)
{
    __shared__ float xts[32][33];
    __shared__ float Ws[32][128];
    int b  = blockIdx.x >> 10;
    int n0 = (blockIdx.x & 1023) << 5;
    int t  = threadIdx.x;

    for (int i = t; i < 32*128; i += 256) Ws[i >> 7][i & 127] = Wq[i];
    for (int i = t; i < 1024; i += 256) {
        int j = i & 31, c = i >> 5;
        xts[j][c] = x[(b*CC + c)*NN + n0 + j];
    }
    __syncthreads();
    for (int i = t; i < 1024; i += 256) {
        int c = i & 31, j = i >> 5;
        float v = xts[j][c] + pos[(n0 + j)*CC + c];
        xts[j][c] = v;
        g_xt[(b*NN + n0 + j)*CC + c] = v;
    }
    __syncthreads();
    int w = t >> 5, lane = t & 31;
    for (int jj = 0; jj < 4; jj++) {
        int j = w*4 + jj;
        float v = xts[j][lane];
        float s = v, ss = v*v;
        #pragma unroll
        for (int o = 16; o > 0; o >>= 1) {
            s  += __shfl_xor_sync(0xffffffffu, s, o);
            ss += __shfl_xor_sync(0xffffffffu, ss, o);
        }
        float mu  = s * (1.0f/32.0f);
        float var = ss * (1.0f/32.0f) - mu*mu;
        float r   = rsqrtf(var + 1e-5f);
        xts[j][lane] = (v - mu) * r * lng[lane] + lnb[lane];
    }
    __syncthreads();
    float acc[16];
    #pragma unroll
    for (int i = 0; i < 16; i++) acc[i] = 0.f;
    int c0 = w * 16;
    #pragma unroll
    for (int kk = 0; kk < 32; kk++) {
        float xv = xts[lane][kk];
        #pragma unroll
        for (int i = 0; i < 16; i++) acc[i] += xv * Ws[kk][c0 + i];
    }
    #pragma unroll
    for (int i = 0; i < 16; i++) {
        int col   = c0 + i;
        int which = col >> 5;
        int ch    = col & 31;
        float* dst = (which == 0) ? g_q : (which == 1) ? g_k :
                     (which == 2) ? g_vca : g_vsa;
        dst[(b*CC + ch)*NN + n0 + lane] = acc[i];
        if (which == 1)
            g_kv16[(size_t)(b*CC + ch)*NN + n0 + lane] = __float2half_rn(acc[i]);
        else if (which == 3)
            g_kv16[(size_t)(128 + b*CC + ch)*NN + n0 + lane] = __float2half_rn(acc[i]);
    }
}

// ---------------- EF weight fp16 prep ----------------
__global__ __launch_bounds__(256) void k_ef_prep(const float* __restrict__ EFw)
{
    int i = blockIdx.x*256 + threadIdx.x;   // over 2M/4 float4s
    float4 v = *reinterpret_cast<const float4*>(EFw + (size_t)i*4);
    __half2 h[2];
    h[0] = __half2(__float2half_rn(v.x), __float2half_rn(v.y));
    h[1] = __half2(__float2half_rn(v.z), __float2half_rn(v.w));
    *reinterpret_cast<uint2*>(g_ef16 + (size_t)i*4) = *reinterpret_cast<uint2*>(h);
}

// ---------------- K2 v2: EF projections via fp16 mma (split-K) ----------------
// D[256 rows][64 p] = kv16 · ef16^T, split over K=NN in KSPLIT chunks of 256.
// grid (KSPLIT, 2): rg=0 -> rows 0..127 (k), rg=1 -> rows 128..255 (v).
__global__ __launch_bounds__(256) void k2_mma()
{
    __shared__ __align__(128) __half Asm[128*64];   // 16 KB
    __shared__ __align__(128) __half Bsm[64*64];    // 8 KB
    int t = threadIdx.x, warp = t >> 5, lane = t & 31;
    int split = blockIdx.x, rg = blockIdx.y;
    const __half* gA = g_kv16 + (size_t)rg*128*NN;
    int nb0 = split*256;

    uint32_t Abase = smem_u32(Asm), Bbase = smem_u32(Bsm);
    float acc[8][4];
    #pragma unroll
    for (int nb = 0; nb < 8; nb++)
        #pragma unroll
        for (int j = 0; j < 4; j++) acc[nb][j] = 0.f;

    int a_rl = (lane & 7) + ((lane >> 3) & 1)*8;
    int a_cs = lane >> 4;
    int b_rn = (lane & 7) + ((lane >> 4) << 3);
    int b_cs = (lane >> 3) & 1;

    for (int st = 0; st < 4; st++) {
        int nb = nb0 + st*64;
        __syncthreads();
        for (int idx = t; idx < 1024; idx += 256) {
            int r = idx >> 3, c = idx & 7;
            float4 v = *reinterpret_cast<const float4*>(gA + (size_t)r*NN + nb + c*8);
            *reinterpret_cast<float4*>(
                reinterpret_cast<char*>(Asm) + SW128(r*128 + c*16)) = v;
        }
        for (int idx = t; idx < 512; idx += 256) {
            int r = idx >> 3, c = idx & 7;
            float4 v = *reinterpret_cast<const float4*>(g_ef16 + (size_t)r*NN + nb + c*8);
            *reinterpret_cast<float4*>(
                reinterpret_cast<char*>(Bsm) + SW128(r*128 + c*16)) = v;
        }
        __syncthreads();
        #pragma unroll
        for (int ks = 0; ks < 4; ks++) {
            uint32_t a[4];
            int row = warp*16 + a_rl;
            ldmx4(a, Abase + SW128(row*128 + (2*ks + a_cs)*16));
            uint32_t bf[16];
            #pragma unroll
            for (int np = 0; np < 4; np++) {
                int rn = np*16 + b_rn;
                ldmx4(&bf[np*4], Bbase + SW128(rn*128 + (2*ks + b_cs)*16));
            }
            #pragma unroll
            for (int nb2 = 0; nb2 < 8; nb2++) {
                int bi = (nb2 >> 1)*4 + (nb2 & 1)*2;
                mma_fp16(acc[nb2], a, bf[bi], bf[bi + 1]);
            }
        }
    }
    int rbase = rg*128 + warp*16;
    #pragma unroll
    for (int nb2 = 0; nb2 < 8; nb2++) {
        int col = nb2*8 + 2*(lane & 3);
        #pragma unroll
        for (int half = 0; half < 2; half++) {
            int row = rbase + (lane >> 2) + half*8;
            *reinterpret_cast<float2*>(&g_part[((size_t)split*256 + row)*64 + col]) =
                make_float2(acc[nb2][half*2], acc[nb2][half*2 + 1]);
        }
    }
}

__global__ __launch_bounds__(256) void k2_proj_reduce(const float* __restrict__ EFb)
{
    int idx = blockIdx.x * 256 + threadIdx.x;   // 0..16383
    int row = idx >> 6, p = idx & 63;
    float s = 0.f;
    for (int c = 0; c < KSPLIT; c++) s += g_part[((size_t)c*256 + row)*64 + p];
    s += EFb[p];
    if (row < 128) g_kproj[row*PP + p] = s;
    else           g_vproj[(row - 128)*PP + p] = s;
}

// ---------------- K3a: gram matrix + L2 norms ----------------
__global__ __launch_bounds__(256) void k3a_gram_partial()
{
    int split = blockIdx.x;
    int bh    = blockIdx.y;
    int t     = threadIdx.x;
    const float* qb = g_q + bh*8*NN;
    const float* kb = g_k + bh*8*NN;

    float v[80];
    #pragma unroll
    for (int i = 0; i < 80; i++) v[i] = 0.f;

    int nend = split*4096 + 4096;
    for (int n = split*4096 + t; n < nend; n += 256) {
        float qv[8], kv[8];
        #pragma unroll
        for (int d = 0; d < 8; d++) { qv[d] = qb[d*NN + n]; kv[d] = kb[d*NN + n]; }
        #pragma unroll
        for (int d = 0; d < 8; d++) {
            v[64 + d] += qv[d]*qv[d];
            v[72 + d] += kv[d]*kv[d];
            #pragma unroll
            for (int e = 0; e < 8; e++) v[d*8 + e] += qv[d]*kv[e];
        }
    }
    __shared__ float wsum[8][80];
    int w = t >> 5, lane = t & 31;
    #pragma unroll
    for (int i = 0; i < 80; i++) {
        float s = v[i];
        #pragma unroll
        for (int o = 16; o > 0; o >>= 1) s += __shfl_xor_sync(0xffffffffu, s, o);
        if (lane == 0) wsum[w][i] = s;
    }
    __syncthreads();
    if (t < 80) {
        float s = 0.f;
        #pragma unroll
        for (int ww = 0; ww < 8; ww++) s += wsum[ww][t];
        g_npart[(split*16 + bh)*80 + t] = s;
    }
}

__global__ __launch_bounds__(128) void k3a_finalize(const float* __restrict__ temp1)
{
    int bh = blockIdx.x;
    int t  = threadIdx.x;
    __shared__ float tot[80];
    __shared__ float qi[8], ki[8];
    if (t < 80) {
        float s = 0.f;
        #pragma unroll
        for (int sp = 0; sp < 8; sp++) s += g_npart[(sp*16 + bh)*80 + t];
        tot[t] = s;
    }
    __syncthreads();
    if (t < 8) {
        float qn = sqrtf(tot[64 + t]);
        float kn = sqrtf(tot[72 + t]);
        qi[t] = 1.0f / fmaxf(qn, 1e-12f);
        ki[t] = 1.0f / fmaxf(kn, 1e-12f);
        g_qinv[bh*8 + t] = qi[t];
    }
    __syncthreads();
    if (t < 8) {
        int h = bh & 3;
        float t1 = temp1[h];
        float sc[8];
        float m = -1e30f;
        #pragma unroll
        for (int e = 0; e < 8; e++) {
            sc[e] = tot[t*8 + e] * qi[t] * ki[e] * t1;
            m = fmaxf(m, sc[e]);
        }
        float sum = 0.f;
        #pragma unroll
        for (int e = 0; e < 8; e++) { sc[e] = __expf(sc[e] - m); sum += sc[e]; }
        float inv = 1.0f / sum;
        #pragma unroll
        for (int e = 0; e < 8; e++) g_attnca[bh*64 + t*8 + e] = sc[e]*inv;
    }
}

// ---------------- K3b ----------------
__global__ __launch_bounds__(128) void k3b_attn(const float* __restrict__ temp2)
{
    int bh = blockIdx.y;
    int n  = blockIdx.x * 128 + threadIdx.x;
    int h  = bh & 3;
    int t  = threadIdx.x;
    __shared__ float kq[8][64], vp[8][64], A[8][8];
    float t2 = temp2[h];
    for (int i = t; i < 512; i += 128) {
        int d = i >> 6, p = i & 63;
        kq[d][p] = g_qinv[bh*8 + d] * g_kproj[(bh*8 + d)*PP + p] * t2;
        vp[d][p] = g_vproj[(bh*8 + d)*PP + p];
    }
    if (t < 64) A[t >> 3][t & 7] = g_attnca[bh*64 + t];
    __syncthreads();

    int base = bh*8*NN + n;
    float qv[8];
    #pragma unroll
    for (int d = 0; d < 8; d++) qv[d] = g_q[base + d*NN];

    float s[64];
    #pragma unroll
    for (int p = 0; p < 64; p++) s[p] = qv[0]*kq[0][p];
    #pragma unroll
    for (int d = 1; d < 8; d++)
        #pragma unroll
        for (int p = 0; p < 64; p++) s[p] += qv[d]*kq[d][p];

    float m = s[0];
    #pragma unroll
    for (int p = 1; p < 64; p++) m = fmaxf(m, s[p]);
    float sum = 0.f;
    #pragma unroll
    for (int p = 0; p < 64; p++) { s[p] = __expf(s[p] - m); sum += s[p]; }
    float inv = 1.0f / sum;

    #pragma unroll
    for (int d = 0; d < 8; d++) {
        float o = 0.f;
        #pragma unroll
        for (int p = 0; p < 64; p++) o += s[p]*vp[d][p];
        g_xsa[base + d*NN] = o * inv;
    }
    float vv[8];
    #pragma unroll
    for (int e = 0; e < 8; e++) vv[e] = g_vca[base + e*NN];
    #pragma unroll
    for (int d = 0; d < 8; d++) {
        float xc = 0.f;
        #pragma unroll
        for (int e = 0; e < 8; e++) xc += A[d][e]*vv[e];
        g_xca[base + d*NN] = xc;
    }
}

// ---------------- K4: combine; write skip ([c][n] and [n][c]) + pad1 (fp16) ----------------
__global__ __launch_bounds__(128) void k4_combine(
    const float* __restrict__ o1w, const float* __restrict__ o1b,
    const float* __restrict__ o2w, const float* __restrict__ o2b,
    const float* __restrict__ gamma)
{
    __shared__ float sa[32][33], ca[32][33], xtl[32][33], resm[32][33];
    __shared__ float w1[16][32], w2[16][32], b1[16], b2[16], gm[32];
    int b  = blockIdx.x >> 10;
    int t0 = (blockIdx.x & 1023) << 5;
    int t  = threadIdx.x;
    int dd   = t0 >> 12;
    int hh   = (t0 >> 10) & 3;
    int nsrc = (t0 & 1023) << 5;

    const float* sap = g_xsa + ((b*NHEAD + hh)*HDIM + dd)*NN + nsrc;
    for (int i = t; i < 1024; i += 128) sa[i >> 5][i & 31] = sap[i];
    for (int i = t; i < 1024; i += 128) {
        int c = i >> 5, ii = i & 31;
        ca[ii][c] = g_xca[(b*CC + c)*NN + t0 + ii];
    }
    for (int i = t; i < 1024; i += 128) {
        int ii = i >> 5, c = i & 31;
        xtl[ii][c] = g_xt[(b*NN + t0 + ii)*CC + c];
    }
    for (int i = t; i < 512; i += 128) {
        w1[i >> 5][i & 31] = o1w[i];
        w2[i >> 5][i & 31] = o2w[i];
    }
    if (t < 16) { b1[t] = o1b[t]; b2[t] = o2b[t]; }
    if (t < 32) gm[t] = gamma[t];
    __syncthreads();

    int ii = t & 31;
    int cg = t >> 5;
    #pragma unroll
    for (int cc = 0; cc < 8; cc++) {
        int c = cg*8 + cc;
        float val;
        if (c < 16) {
            float s = b1[c];
            #pragma unroll
            for (int k = 0; k < 32; k++) s += sa[ii][k]*w1[c][k];
            val = s;
        } else {
            int j = c - 16;
            float s = b2[j];
            #pragma unroll
            for (int k = 0; k < 32; k++) s += ca[ii][k]*w2[j][k];
            val = s;
        }
        float r = xtl[ii][c] + gm[c]*val;
        resm[ii][c] = r;
        g_skip[(b*CC + c)*NN + t0 + ii] = r;
    }
    __syncthreads();
    int tok = t >> 2, cgp = t & 3;
    int n   = t0 + tok;
    {
        float4 v0 = make_float4(resm[tok][cgp*8],   resm[tok][cgp*8+1],
                                resm[tok][cgp*8+2], resm[tok][cgp*8+3]);
        float4 v1 = make_float4(resm[tok][cgp*8+4], resm[tok][cgp*8+5],
                                resm[tok][cgp*8+6], resm[tok][cgp*8+7]);
        float4* d = reinterpret_cast<float4*>(g_skiptm + ((size_t)b*NN + n)*CC + cgp*8);
        d[0] = v0; d[1] = v1;
    }
    int npad = ((n >> 10) + 1)*1156 + (((n >> 5) & 31) + 1)*34 + (n & 31) + 1;
    __half2 h[4];
    #pragma unroll
    for (int j = 0; j < 4; j++)
        h[j] = __half2(__float2half_rn(resm[tok][cgp*8 + 2*j]),
                       __float2half_rn(resm[tok][cgp*8 + 2*j + 1]));
    *reinterpret_cast<uint4*>(g_pad1 + ((size_t)b*PADSTR + GUARD + npad)*32 + cgp*8) =
        *reinterpret_cast<uint4*>(h);
}

// ---------------- weight prep: fp16 images [tap][co][ci] ----------------
__global__ __launch_bounds__(256) void kw_prep(const float* __restrict__ c1w,
                                               const float* __restrict__ c2w)
{
    int i = blockIdx.x*256 + threadIdx.x;      // 0 .. 2*27648
    if (i >= 2*27648) return;
    int which = (i >= 27648);
    int j = i - which*27648;                   // j = (co*32+ci)*27 + tap
    const float* w = which ? c2w : c1w;
    __half* out = which ? g_wimg2 : g_wimg1;
    int tap = j % 27; int r = j / 27; int ci = r & 31; int co = r >> 5;
    out[(tap*32 + co)*32 + ci] = __float2half_rn(w[j]);
}

// ---------------- conv via mma.sync v3: single-chain fp16, K=32, 64B rows ----------------
template<int MODE>
__global__ __launch_bounds__(256) void conv_mma(
    const float* __restrict__ cb, const float* __restrict__ bg,
    const float* __restrict__ bb, const float* __restrict__ bm,
    const float* __restrict__ bv)
{
    __shared__ __align__(128) __half Asm[258*32];   // 16.5 KB
    __shared__ __align__(128) __half Bsm[3*32*32];  // 6 KB
    __shared__ float scs[32], bss[32];

    const __half* gA = (MODE == 1) ? g_pad1 : g_pad2;
    const __half* gW = (MODE == 1) ? g_wimg1 : g_wimg2;

    int t = threadIdx.x, warp = t >> 5, lane = t & 31;
    int base = 1024 + blockIdx.x * 256;
    int b    = blockIdx.y;
    long volr = (long)b*PADSTR + GUARD;

    if (t < 32) {
        float a = bg[t]*rsqrtf(bv[t] + 1e-5f);
        scs[t] = a;
        bss[t] = (cb[t] - bm[t])*a + bb[t];
    }

    uint32_t Abase = smem_u32(Asm), Bbase = smem_u32(Bsm);
    float acc[2][4][4];
    #pragma unroll
    for (int mt = 0; mt < 2; mt++)
        #pragma unroll
        for (int nb = 0; nb < 4; nb++)
            #pragma unroll
            for (int j = 0; j < 4; j++) acc[mt][nb][j] = 0.f;

    int a_rl = (lane & 7) + ((lane >> 3) & 1)*8;
    int a_cs = lane >> 4;
    int b_rn = (lane & 7) + ((lane >> 4) << 3);
    int b_cs = (lane >> 3) & 1;

    for (int kzy = 0; kzy < 9; kzy++) {
        int kz = kzy/3, ky = kzy - kz*3;
        __syncthreads();
        long rowb = volr + base + (kz - 1)*1156 + (ky - 1)*34 - 1;
        for (int idx = t; idx < 1032; idx += 256) {
            int r = idx >> 2, c = idx & 3;
            float4 v = *reinterpret_cast<const float4*>(gA + (rowb + r)*32 + c*8);
            *reinterpret_cast<float4*>(
                reinterpret_cast<char*>(Asm) + SW64(r*64 + c*16)) = v;
        }
        for (int idx = t; idx < 384; idx += 256) {
            int row = idx >> 2, c = idx & 3;
            int dx = row >> 5, co = row & 31;
            float4 v = *reinterpret_cast<const float4*>(
                gW + ((size_t)(kzy*3 + dx)*32 + co)*32 + c*8);
            *reinterpret_cast<float4*>(
                reinterpret_cast<char*>(Bsm) + dx*2048 + SW64(co*64 + c*16)) = v;
        }
        __syncthreads();
        #pragma unroll
        for (int dx = 0; dx < 3; dx++) {
            #pragma unroll
            for (int ks = 0; ks < 2; ks++) {
                uint32_t a[2][4];
                #pragma unroll
                for (int mt = 0; mt < 2; mt++) {
                    int row = warp*32 + mt*16 + a_rl + dx;
                    ldmx4(a[mt], Abase + SW64(row*64 + (2*ks + a_cs)*16));
                }
                uint32_t bf[8];
                #pragma unroll
                for (int np = 0; np < 2; np++) {
                    int rn = np*16 + b_rn;
                    ldmx4(&bf[np*4],
                          Bbase + dx*2048 + SW64(rn*64 + (2*ks + b_cs)*16));
                }
                #pragma unroll
                for (int mt = 0; mt < 2; mt++)
                    #pragma unroll
                    for (int nb = 0; nb < 4; nb++) {
                        int bi = (nb >> 1)*4 + (nb & 1)*2;
                        mma_fp16(acc[mt][nb], a[mt], bf[bi], bf[bi + 1]);
                    }
            }
        }
    }

    int cl = lane & 3;
    #pragma unroll
    for (int mt = 0; mt < 2; mt++)
        #pragma unroll
        for (int half = 0; half < 2; half++) {
            int m = base + warp*32 + mt*16 + (lane >> 2) + half*8;
            int zp = m / 1156; int rem = m - zp*1156;
            int yp = rem / 34; int xp = rem - yp*34;
            if (zp < 1 || zp > 32 || yp < 1 || yp > 32 || xp < 1 || xp > 32) continue;
            if (MODE == 1) {
                __half* dst = g_pad2 + (volr + m)*32;
                #pragma unroll
                for (int nb = 0; nb < 4; nb++) {
                    int co = nb*8 + 2*cl;
                    float v0 = acc[mt][nb][half*2]    *scs[co]   + bss[co];
                    float v1 = acc[mt][nb][half*2 + 1]*scs[co+1] + bss[co+1];
                    v0 = (v0 > 0.f) ? v0 : 0.01f*v0;
                    v1 = (v1 > 0.f) ? v1 : 0.01f*v1;
                    *reinterpret_cast<__half2*>(dst + co) =
                        __half2(__float2half_rn(v0), __float2half_rn(v1));
                }
            } else {
                int n = (zp - 1)*1024 + (yp - 1)*32 + (xp - 1);
                const float* sk = g_skiptm + ((size_t)b*NN + n)*CC;
                float* dst = g_y2tm + ((size_t)b*NN + n)*CC;
                #pragma unroll
                for (int nb = 0; nb < 4; nb++) {
                    int co = nb*8 + 2*cl;
                    float2 s = *reinterpret_cast<const float2*>(sk + co);
                    float v0 = acc[mt][nb][half*2]    *scs[co]   + bss[co]   + s.x;
                    float v1 = acc[mt][nb][half*2 + 1]*scs[co+1] + bss[co+1] + s.y;
                    v0 = (v0 > 0.f) ? v0 : 0.01f*v0;
                    v1 = (v1 > 0.f) ? v1 : 0.01f*v1;
                    *reinterpret_cast<float2*>(dst + co) = make_float2(v0, v1);
                }
            }
        }
}

// ---------------- final: 1x1 conv residual (reads token-major y2) ----------------
__global__ __launch_bounds__(256) void k_final(
    const float* __restrict__ wp, const float* __restrict__ bp,
    float* __restrict__ outp)
{
    __shared__ float ys[64][33];
    __shared__ float wsm[32][32];
    __shared__ float bsh[32];
    int b  = blockIdx.x >> 9;
    int n0 = (blockIdx.x & 511) << 6;
    int t  = threadIdx.x;
    for (int i = t; i < 2048; i += 256) {
        int nn = i >> 5, ci = i & 31;
        ys[nn][ci] = g_y2tm[((size_t)b*NN + n0 + nn)*CC + ci];
    }
    for (int i = t; i < 1024; i += 256) wsm[i >> 5][i & 31] = wp[i];
    if (t < 32) bsh[t] = bp[t];
    __syncthreads();
    int nn = t & 63;
    int cg = t >> 6;
    #pragma unroll
    for (int cc = 0; cc < 8; cc++) {
        int co = cg*8 + cc;
        float s = bsh[co];
        #pragma unroll
        for (int ci = 0; ci < 32; ci++) s += wsm[co][ci]*ys[nn][ci];
        int idx = (b*32 + co)*NN + n0 + nn;
        outp[idx] = g_skip[idx] + s;
    }
}

// ---------------- launch ----------------
extern "C" void kernel_launch(void* const* d_in, const int* in_sizes, int n_in,
                              void* d_out, int out_size)
{
    const float* x    = (const float*)d_in[0];
    const float* pos  = (const float*)d_in[1];
    const float* lng  = (const float*)d_in[2];
    const float* lnb  = (const float*)d_in[3];
    const float* gam  = (const float*)d_in[4];
    const float* Wq   = (const float*)d_in[5];
    const float* EFw  = (const float*)d_in[6];
    const float* EFb  = (const float*)d_in[7];
    const float* t1   = (const float*)d_in[8];
    const float* t2   = (const float*)d_in[9];
    const float* o1w  = (const float*)d_in[10];
    const float* o1b  = (const float*)d_in[11];
    const float* o2w  = (const float*)d_in[12];
    const float* o2b  = (const float*)d_in[13];
    const float* c1w  = (const float*)d_in[14];
    const float* c1b  = (const float*)d_in[15];
    const float* b1g  = (const float*)d_in[16];
    const float* b1b  = (const float*)d_in[17];
    const float* b1m  = (const float*)d_in[18];
    const float* b1v  = (const float*)d_in[19];
    const float* c2w  = (const float*)d_in[20];
    const float* c2b  = (const float*)d_in[21];
    const float* b2g  = (const float*)d_in[22];
    const float* b2b  = (const float*)d_in[23];
    const float* b2m  = (const float*)d_in[24];
    const float* b2v  = (const float*)d_in[25];
    const float* cpw  = (const float*)d_in[26];
    const float* cpb  = (const float*)d_in[27];
    float* outp = (float*)d_out;

    // launch index 3 = k2_mma (profiled this round)
    k1_tok_ln_qkvv<<<4096, 256>>>(x, pos, lng, lnb, Wq);          // 0
    k3a_gram_partial<<<dim3(8, 16), 256>>>();                      // 1
    k_ef_prep<<<2048, 256>>>(EFw);                                 // 2
    k2_mma<<<dim3(KSPLIT, 2), 256>>>();                            // 3  <- profiled
    k2_proj_reduce<<<64, 256>>>(EFb);                              // 4
    k3a_finalize<<<16, 128>>>(t1);                                 // 5
    kw_prep<<<216, 256>>>(c1w, c2w);                               // 6
    k3b_attn<<<dim3(256, 16), 128>>>(t2);                          // 7
    k4_combine<<<4096, 128>>>(o1w, o1b, o2w, o2b, gam);            // 8
    conv_mma<1><<<dim3(NTILE2, BB), 256>>>(c1b, b1g, b1b, b1m, b1v);
    conv_mma<2><<<dim3(NTILE2, BB), 256>>>(c2b, b2g, b2b, b2m, b2v);
    k_final<<<2048, 256>>>(cpw, cpb, outp);
}

// round 15
// speedup vs baseline: 3.8958x; 1.1956x over previous
#include <cuda_runtime.h>
#include <cuda_fp16.h>
#include <math.h>
#include <stdint.h>

#define BB 4
#define CC 32
#define NHEAD 4
#define HDIM 8
#define NN 32768
#define PP 64
#define KSPLIT 128

#define PADN   39304            // 34*34*34
#define GUARD  1536
#define PADSTR (PADN + 2*GUARD) // rows per batch
#define NTILE2 146              // tokens [1024, 38400) in 256-token blocks

// ---------------- scratch (static device memory; no allocations) ----------------
static __device__ float g_xt  [BB*NN*CC];
static __device__ float g_part[(size_t)KSPLIT*256*64];   // split-K partials
static __device__ float g_kproj[BB*CC*PP];
static __device__ float g_vproj[BB*CC*PP];
static __device__ float g_npart[8*16*80];
static __device__ float g_qinv[BB*CC];
static __device__ float g_attnca[BB*NHEAD*HDIM*HDIM];
static __device__ float g_skip[BB*CC*NN];      // [b][c][n] for k_final
static __device__ float g_skiptm[BB*NN*CC];    // [b][n][c] for conv2 residual
static __device__ float g_y2tm [BB*NN*CC];     // [b][n][c] conv2 output
// fp16 attention tensors (gamma-damped branch)
static __device__ __align__(16) __half g_q16 [(size_t)16*NN*8];  // [b*4+h][n][d]
static __device__ __align__(16) __half g_k16 [(size_t)16*NN*8];  // [b*4+h][n][d]
static __device__ __align__(16) __half g_vca16[(size_t)16*NN*8]; // [b*4+h][n][d]
static __device__ __align__(16) __half g_kv16[(size_t)256*NN];   // rows 0-127 k, 128-255 v_sa
static __device__ __align__(16) __half g_ef16[(size_t)PP*NN];
static __device__ __align__(16) __half g_xsa16[(size_t)128*NN];  // [bh*8+d][n]
static __device__ __align__(16) __half g_xca16[(size_t)128*NN];  // [b*32+c][n]
// padded token-major conv activations: [b][padtoken][32 fp16]
static __device__ __align__(16) __half g_pad1[(size_t)BB*PADSTR*32];
static __device__ __align__(16) __half g_pad2[(size_t)BB*PADSTR*32];
// weight images: [tap][co(32)][ci(32)] fp16
static __device__ __align__(16) __half g_wimg1[27*32*32];
static __device__ __align__(16) __half g_wimg2[27*32*32];

// ---------------- helpers ----------------
#define SW64(o)  ((o) ^ (((o) >> 3) & 0x30))
#define SW128(o) ((o) ^ (((o) >> 3) & 0x70))

__device__ __forceinline__ uint32_t smem_u32(const void* p) {
    uint32_t a;
    asm("{ .reg .u64 t; cvta.to.shared.u64 t, %1; cvt.u32.u64 %0, t; }" : "=r"(a) : "l"(p));
    return a;
}
__device__ __forceinline__ void ldmx4(uint32_t* r, uint32_t addr) {
    asm volatile("ldmatrix.sync.aligned.m8n8.x4.shared.b16 {%0,%1,%2,%3}, [%4];"
                 : "=r"(r[0]), "=r"(r[1]), "=r"(r[2]), "=r"(r[3]) : "r"(addr));
}
__device__ __forceinline__ void mma_fp16(float* d, const uint32_t* a, uint32_t b0, uint32_t b1) {
    asm volatile("mma.sync.aligned.m16n8k16.row.col.f32.f16.f16.f32 "
                 "{%0,%1,%2,%3}, {%4,%5,%6,%7}, {%8,%9}, {%0,%1,%2,%3};"
                 : "+f"(d[0]), "+f"(d[1]), "+f"(d[2]), "+f"(d[3])
                 : "r"(a[0]), "r"(a[1]), "r"(a[2]), "r"(a[3]), "r"(b0), "r"(b1));
}

// ---------------- K1: transpose+pos, layernorm, QKVV GEMM (fp16 outputs) ----------------
__global__ __launch_bounds__(256) void k1_tok_ln_qkvv(
    const float* __restrict__ x, const float* __restrict__ pos,
    const float* __restrict__ lng, const float* __restrict__ lnb,
    const float* __restrict__ Wq)
{
    __shared__ float xts[32][33];
    __shared__ __half2 Wh[32][64];      // [kk][colpair]
    int b  = blockIdx.x >> 10;
    int n0 = (blockIdx.x & 1023) << 5;
    int t  = threadIdx.x;

    for (int i = t; i < 32*64; i += 256) {
        int row = i >> 6, j = i & 63;
        float2 v = *reinterpret_cast<const float2*>(Wq + row*128 + 2*j);
        Wh[row][j] = __floats2half2_rn(v.x, v.y);
    }
    for (int i = t; i < 1024; i += 256) {
        int j = i & 31, c = i >> 5;
        xts[j][c] = x[(b*CC + c)*NN + n0 + j];
    }
    __syncthreads();
    for (int i = t; i < 1024; i += 256) {
        int c = i & 31, j = i >> 5;
        float v = xts[j][c] + pos[(n0 + j)*CC + c];
        xts[j][c] = v;
        g_xt[(b*NN + n0 + j)*CC + c] = v;
    }
    __syncthreads();
    int w = t >> 5, lane = t & 31;
    for (int jj = 0; jj < 4; jj++) {
        int j = w*4 + jj;
        float v = xts[j][lane];
        float s = v, ss = v*v;
        #pragma unroll
        for (int o = 16; o > 0; o >>= 1) {
            s  += __shfl_xor_sync(0xffffffffu, s, o);
            ss += __shfl_xor_sync(0xffffffffu, ss, o);
        }
        float mu  = s * (1.0f/32.0f);
        float var = ss * (1.0f/32.0f) - mu*mu;
        float r   = rsqrtf(var + 1e-5f);
        xts[j][lane] = (v - mu) * r * lng[lane] + lnb[lane];
    }
    __syncthreads();
    // fp16 GEMM: warp w -> colpairs 8w..8w+7, lane = token
    __half2 acc2[8];
    #pragma unroll
    for (int i = 0; i < 8; i++) acc2[i] = __floats2half2_rn(0.f, 0.f);
    #pragma unroll
    for (int kk = 0; kk < 32; kk++) {
        __half2 xv2 = __float2half2_rn(xts[lane][kk]);
        #pragma unroll
        for (int i = 0; i < 8; i++)
            acc2[i] = __hfma2(xv2, Wh[kk][w*8 + i], acc2[i]);
    }
    int n = n0 + lane;
    int which = w >> 1;           // 0=q,1=k,2=vca,3=vsa
    int hA = (w & 1) * 2;
    uint32_t* au = reinterpret_cast<uint32_t*>(acc2);
    uint4 u0 = make_uint4(au[0], au[1], au[2], au[3]);
    uint4 u1 = make_uint4(au[4], au[5], au[6], au[7]);
    if (which == 0) {
        *reinterpret_cast<uint4*>(g_q16 + ((size_t)(b*4 + hA)*NN + n)*8)     = u0;
        *reinterpret_cast<uint4*>(g_q16 + ((size_t)(b*4 + hA + 1)*NN + n)*8) = u1;
    } else if (which == 1) {
        *reinterpret_cast<uint4*>(g_k16 + ((size_t)(b*4 + hA)*NN + n)*8)     = u0;
        *reinterpret_cast<uint4*>(g_k16 + ((size_t)(b*4 + hA + 1)*NN + n)*8) = u1;
        #pragma unroll
        for (int i = 0; i < 8; i++) {
            int ch = (w & 1)*16 + 2*i;
            g_kv16[(size_t)(b*32 + ch)*NN + n]     = __low2half(acc2[i]);
            g_kv16[(size_t)(b*32 + ch + 1)*NN + n] = __high2half(acc2[i]);
        }
    } else if (which == 2) {
        *reinterpret_cast<uint4*>(g_vca16 + ((size_t)(b*4 + hA)*NN + n)*8)     = u0;
        *reinterpret_cast<uint4*>(g_vca16 + ((size_t)(b*4 + hA + 1)*NN + n)*8) = u1;
    } else {
        #pragma unroll
        for (int i = 0; i < 8; i++) {
            int ch = (w & 1)*16 + 2*i;
            g_kv16[(size_t)(128 + b*32 + ch)*NN + n]     = __low2half(acc2[i]);
            g_kv16[(size_t)(128 + b*32 + ch + 1)*NN + n] = __high2half(acc2[i]);
        }
    }
}

// ---------------- EF weight fp16 prep ----------------
__global__ __launch_bounds__(256) void k_ef_prep(const float* __restrict__ EFw)
{
    int i = blockIdx.x*256 + threadIdx.x;   // over 2M/4 float4s
    float4 v = *reinterpret_cast<const float4*>(EFw + (size_t)i*4);
    __half2 h[2];
    h[0] = __half2(__float2half_rn(v.x), __float2half_rn(v.y));
    h[1] = __half2(__float2half_rn(v.z), __float2half_rn(v.w));
    *reinterpret_cast<uint2*>(g_ef16 + (size_t)i*4) = *reinterpret_cast<uint2*>(h);
}

// ---------------- K2: EF projections via fp16 mma (split-K) ----------------
__global__ __launch_bounds__(256) void k2_mma()
{
    __shared__ __align__(128) __half Asm[128*64];   // 16 KB
    __shared__ __align__(128) __half Bsm[64*64];    // 8 KB
    int t = threadIdx.x, warp = t >> 5, lane = t & 31;
    int split = blockIdx.x, rg = blockIdx.y;
    const __half* gA = g_kv16 + (size_t)rg*128*NN;
    int nb0 = split*256;

    uint32_t Abase = smem_u32(Asm), Bbase = smem_u32(Bsm);
    float acc[8][4];
    #pragma unroll
    for (int nb = 0; nb < 8; nb++)
        #pragma unroll
        for (int j = 0; j < 4; j++) acc[nb][j] = 0.f;

    int a_rl = (lane & 7) + ((lane >> 3) & 1)*8;
    int a_cs = lane >> 4;
    int b_rn = (lane & 7) + ((lane >> 4) << 3);
    int b_cs = (lane >> 3) & 1;

    for (int st = 0; st < 4; st++) {
        int nb = nb0 + st*64;
        __syncthreads();
        for (int idx = t; idx < 1024; idx += 256) {
            int r = idx >> 3, c = idx & 7;
            float4 v = *reinterpret_cast<const float4*>(gA + (size_t)r*NN + nb + c*8);
            *reinterpret_cast<float4*>(
                reinterpret_cast<char*>(Asm) + SW128(r*128 + c*16)) = v;
        }
        for (int idx = t; idx < 512; idx += 256) {
            int r = idx >> 3, c = idx & 7;
            float4 v = *reinterpret_cast<const float4*>(g_ef16 + (size_t)r*NN + nb + c*8);
            *reinterpret_cast<float4*>(
                reinterpret_cast<char*>(Bsm) + SW128(r*128 + c*16)) = v;
        }
        __syncthreads();
        #pragma unroll
        for (int ks = 0; ks < 4; ks++) {
            uint32_t a[4];
            int row = warp*16 + a_rl;
            ldmx4(a, Abase + SW128(row*128 + (2*ks + a_cs)*16));
            uint32_t bf[16];
            #pragma unroll
            for (int np = 0; np < 4; np++) {
                int rn = np*16 + b_rn;
                ldmx4(&bf[np*4], Bbase + SW128(rn*128 + (2*ks + b_cs)*16));
            }
            #pragma unroll
            for (int nb2 = 0; nb2 < 8; nb2++) {
                int bi = (nb2 >> 1)*4 + (nb2 & 1)*2;
                mma_fp16(acc[nb2], a, bf[bi], bf[bi + 1]);
            }
        }
    }
    int rbase = rg*128 + warp*16;
    #pragma unroll
    for (int nb2 = 0; nb2 < 8; nb2++) {
        int col = nb2*8 + 2*(lane & 3);
        #pragma unroll
        for (int half = 0; half < 2; half++) {
            int row = rbase + (lane >> 2) + half*8;
            *reinterpret_cast<float2*>(&g_part[((size_t)split*256 + row)*64 + col]) =
                make_float2(acc[nb2][half*2], acc[nb2][half*2 + 1]);
        }
    }
}

__global__ __launch_bounds__(256) void k2_proj_reduce(const float* __restrict__ EFb)
{
    int idx = blockIdx.x * 256 + threadIdx.x;   // 0..16383
    int row = idx >> 6, p = idx & 63;
    float s = 0.f;
    for (int c = 0; c < KSPLIT; c++) s += g_part[((size_t)c*256 + row)*64 + p];
    s += EFb[p];
    if (row < 128) g_kproj[row*PP + p] = s;
    else           g_vproj[(row - 128)*PP + p] = s;
}

// ---------------- K3a: gram matrix + L2 norms (fp16 inputs) ----------------
__global__ __launch_bounds__(256) void k3a_gram_partial()
{
    int split = blockIdx.x;
    int bh    = blockIdx.y;
    int t     = threadIdx.x;
    const __half* qb = g_q16 + (size_t)bh*NN*8;
    const __half* kb = g_k16 + (size_t)bh*NN*8;

    float v[80];
    #pragma unroll
    for (int i = 0; i < 80; i++) v[i] = 0.f;

    int nend = split*4096 + 4096;
    for (int n = split*4096 + t; n < nend; n += 256) {
        uint4 qu = *reinterpret_cast<const uint4*>(qb + (size_t)n*8);
        uint4 ku = *reinterpret_cast<const uint4*>(kb + (size_t)n*8);
        const __half2* qh = reinterpret_cast<const __half2*>(&qu);
        const __half2* kh = reinterpret_cast<const __half2*>(&ku);
        float qv[8], kv[8];
        #pragma unroll
        for (int j = 0; j < 4; j++) {
            float2 fq = __half22float2(qh[j]);
            float2 fk = __half22float2(kh[j]);
            qv[2*j] = fq.x; qv[2*j + 1] = fq.y;
            kv[2*j] = fk.x; kv[2*j + 1] = fk.y;
        }
        #pragma unroll
        for (int d = 0; d < 8; d++) {
            v[64 + d] += qv[d]*qv[d];
            v[72 + d] += kv[d]*kv[d];
            #pragma unroll
            for (int e = 0; e < 8; e++) v[d*8 + e] += qv[d]*kv[e];
        }
    }
    __shared__ float wsum[8][80];
    int w = t >> 5, lane = t & 31;
    #pragma unroll
    for (int i = 0; i < 80; i++) {
        float s = v[i];
        #pragma unroll
        for (int o = 16; o > 0; o >>= 1) s += __shfl_xor_sync(0xffffffffu, s, o);
        if (lane == 0) wsum[w][i] = s;
    }
    __syncthreads();
    if (t < 80) {
        float s = 0.f;
        #pragma unroll
        for (int ww = 0; ww < 8; ww++) s += wsum[ww][t];
        g_npart[(split*16 + bh)*80 + t] = s;
    }
}

__global__ __launch_bounds__(128) void k3a_finalize(const float* __restrict__ temp1)
{
    int bh = blockIdx.x;
    int t  = threadIdx.x;
    __shared__ float tot[80];
    __shared__ float qi[8], ki[8];
    if (t < 80) {
        float s = 0.f;
        #pragma unroll
        for (int sp = 0; sp < 8; sp++) s += g_npart[(sp*16 + bh)*80 + t];
        tot[t] = s;
    }
    __syncthreads();
    if (t < 8) {
        float qn = sqrtf(tot[64 + t]);
        float kn = sqrtf(tot[72 + t]);
        qi[t] = 1.0f / fmaxf(qn, 1e-12f);
        ki[t] = 1.0f / fmaxf(kn, 1e-12f);
        g_qinv[bh*8 + t] = qi[t];
    }
    __syncthreads();
    if (t < 8) {
        int h = bh & 3;
        float t1 = temp1[h];
        float sc[8];
        float m = -1e30f;
        #pragma unroll
        for (int e = 0; e < 8; e++) {
            sc[e] = tot[t*8 + e] * qi[t] * ki[e] * t1;
            m = fmaxf(m, sc[e]);
        }
        float sum = 0.f;
        #pragma unroll
        for (int e = 0; e < 8; e++) { sc[e] = __expf(sc[e] - m); sum += sc[e]; }
        float inv = 1.0f / sum;
        #pragma unroll
        for (int e = 0; e < 8; e++) g_attnca[bh*64 + t*8 + e] = sc[e]*inv;
    }
}

// ---------------- K3b: spatial attention + channel-attn apply (half2 math) ----------------
__global__ __launch_bounds__(128) void k3b_attn(const float* __restrict__ temp2)
{
    int bh = blockIdx.y;
    int n  = blockIdx.x * 128 + threadIdx.x;
    int h  = bh & 3;
    int t  = threadIdx.x;
    __shared__ __half2 kq2[8][32], vp2[8][32];
    __shared__ float A[8][8];
    float t2 = temp2[h];
    for (int i = t; i < 256; i += 128) {
        int d = i >> 5, pp = i & 31;
        float qinv = g_qinv[bh*8 + d];
        float2 kp = *reinterpret_cast<const float2*>(&g_kproj[(bh*8 + d)*PP + 2*pp]);
        float2 vp = *reinterpret_cast<const float2*>(&g_vproj[(bh*8 + d)*PP + 2*pp]);
        kq2[d][pp] = __floats2half2_rn(qinv*kp.x*t2, qinv*kp.y*t2);
        vp2[d][pp] = __floats2half2_rn(vp.x, vp.y);
    }
    if (t < 64) A[t >> 3][t & 7] = g_attnca[bh*64 + t];
    __syncthreads();

    // load q (8 halves, one uint4)
    uint4 qu = *reinterpret_cast<const uint4*>(g_q16 + ((size_t)bh*NN + n)*8);
    const __half* qh = reinterpret_cast<const __half*>(&qu);
    __half2 qv2[8];
    #pragma unroll
    for (int d = 0; d < 8; d++) qv2[d] = __half2half2(qh[d]);

    __half2 s2[32];
    #pragma unroll
    for (int pp = 0; pp < 32; pp++) s2[pp] = __hmul2(qv2[0], kq2[0][pp]);
    #pragma unroll
    for (int d = 1; d < 8; d++)
        #pragma unroll
        for (int pp = 0; pp < 32; pp++) s2[pp] = __hfma2(qv2[d], kq2[d][pp], s2[pp]);

    float s[64];
    #pragma unroll
    for (int pp = 0; pp < 32; pp++) {
        float2 f = __half22float2(s2[pp]);
        s[2*pp] = f.x; s[2*pp + 1] = f.y;
    }
    float m = s[0];
    #pragma unroll
    for (int p = 1; p < 64; p++) m = fmaxf(m, s[p]);
    float sum = 0.f;
    #pragma unroll
    for (int p = 0; p < 64; p++) { s[p] = __expf(s[p] - m); sum += s[p]; }
    float inv = 1.0f / sum;

    __half2 w2[32];
    #pragma unroll
    for (int pp = 0; pp < 32; pp++)
        w2[pp] = __floats2half2_rn(s[2*pp]*inv, s[2*pp + 1]*inv);

    #pragma unroll
    for (int d = 0; d < 8; d++) {
        __half2 o2 = __hmul2(w2[0], vp2[d][0]);
        #pragma unroll
        for (int pp = 1; pp < 32; pp++) o2 = __hfma2(w2[pp], vp2[d][pp], o2);
        float2 f = __half22float2(o2);
        g_xsa16[(size_t)(bh*8 + d)*NN + n] = __float2half_rn(f.x + f.y);
    }
    // channel attention
    uint4 vu = *reinterpret_cast<const uint4*>(g_vca16 + ((size_t)bh*NN + n)*8);
    const __half2* vh = reinterpret_cast<const __half2*>(&vu);
    float vv[8];
    #pragma unroll
    for (int j = 0; j < 4; j++) {
        float2 f = __half22float2(vh[j]);
        vv[2*j] = f.x; vv[2*j + 1] = f.y;
    }
    #pragma unroll
    for (int d = 0; d < 8; d++) {
        float xc = 0.f;
        #pragma unroll
        for (int e = 0; e < 8; e++) xc += A[d][e]*vv[e];
        g_xca16[(size_t)(bh*8 + d)*NN + n] = __float2half_rn(xc);
    }
}

// ---------------- K4: combine; write skip ([c][n] and [n][c]) + pad1 (fp16) ----------------
__global__ __launch_bounds__(128) void k4_combine(
    const float* __restrict__ o1w, const float* __restrict__ o1b,
    const float* __restrict__ o2w, const float* __restrict__ o2b,
    const float* __restrict__ gamma)
{
    __shared__ float sa[32][33], ca[32][33], xtl[32][33], resm[32][33];
    __shared__ float w1[16][32], w2[16][32], b1[16], b2[16], gm[32];
    int b  = blockIdx.x >> 10;
    int t0 = (blockIdx.x & 1023) << 5;
    int t  = threadIdx.x;
    int dd   = t0 >> 12;
    int hh   = (t0 >> 10) & 3;
    int nsrc = (t0 & 1023) << 5;

    const __half* sap = g_xsa16 + (size_t)((b*4 + hh)*8 + dd)*NN + nsrc;
    for (int i = t; i < 1024; i += 128) sa[i >> 5][i & 31] = __half2float(sap[i]);
    for (int i = t; i < 1024; i += 128) {
        int c = i >> 5, ii = i & 31;
        ca[ii][c] = __half2float(g_xca16[(size_t)(b*CC + c)*NN + t0 + ii]);
    }
    for (int i = t; i < 1024; i += 128) {
        int ii = i >> 5, c = i & 31;
        xtl[ii][c] = g_xt[(b*NN + t0 + ii)*CC + c];
    }
    for (int i = t; i < 512; i += 128) {
        w1[i >> 5][i & 31] = o1w[i];
        w2[i >> 5][i & 31] = o2w[i];
    }
    if (t < 16) { b1[t] = o1b[t]; b2[t] = o2b[t]; }
    if (t < 32) gm[t] = gamma[t];
    __syncthreads();

    int ii = t & 31;
    int cg = t >> 5;
    #pragma unroll
    for (int cc = 0; cc < 8; cc++) {
        int c = cg*8 + cc;
        float val;
        if (c < 16) {
            float s = b1[c];
            #pragma unroll
            for (int k = 0; k < 32; k++) s += sa[ii][k]*w1[c][k];
            val = s;
        } else {
            int j = c - 16;
            float s = b2[j];
            #pragma unroll
            for (int k = 0; k < 32; k++) s += ca[ii][k]*w2[j][k];
            val = s;
        }
        float r = xtl[ii][c] + gm[c]*val;
        resm[ii][c] = r;
        g_skip[(b*CC + c)*NN + t0 + ii] = r;
    }
    __syncthreads();
    int tok = t >> 2, cgp = t & 3;
    int n   = t0 + tok;
    {
        float4 v0 = make_float4(resm[tok][cgp*8],   resm[tok][cgp*8+1],
                                resm[tok][cgp*8+2], resm[tok][cgp*8+3]);
        float4 v1 = make_float4(resm[tok][cgp*8+4], resm[tok][cgp*8+5],
                                resm[tok][cgp*8+6], resm[tok][cgp*8+7]);
        float4* d = reinterpret_cast<float4*>(g_skiptm + ((size_t)b*NN + n)*CC + cgp*8);
        d[0] = v0; d[1] = v1;
    }
    int npad = ((n >> 10) + 1)*1156 + (((n >> 5) & 31) + 1)*34 + (n & 31) + 1;
    __half2 h[4];
    #pragma unroll
    for (int j = 0; j < 4; j++)
        h[j] = __half2(__float2half_rn(resm[tok][cgp*8 + 2*j]),
                       __float2half_rn(resm[tok][cgp*8 + 2*j + 1]));
    *reinterpret_cast<uint4*>(g_pad1 + ((size_t)b*PADSTR + GUARD + npad)*32 + cgp*8) =
        *reinterpret_cast<uint4*>(h);
}

// ---------------- weight prep: fp16 images [tap][co][ci] ----------------
__global__ __launch_bounds__(256) void kw_prep(const float* __restrict__ w, int which)
{
    int j = blockIdx.x*256 + threadIdx.x;      // 0 .. 27648
    if (j >= 27648) return;
    __half* out = which ? g_wimg2 : g_wimg1;
    int tap = j % 27; int r = j / 27; int ci = r & 31; int co = r >> 5;
    out[(tap*32 + co)*32 + ci] = __float2half_rn(w[j]);
}

// ---------------- conv via mma.sync: single-chain fp16, K=32, 64B rows ----------------
template<int MODE>
__global__ __launch_bounds__(256) void conv_mma(
    const float* __restrict__ cb, const float* __restrict__ bg,
    const float* __restrict__ bb, const float* __restrict__ bm,
    const float* __restrict__ bv)
{
    __shared__ __align__(128) __half Asm[258*32];   // 16.5 KB
    __shared__ __align__(128) __half Bsm[3*32*32];  // 6 KB
    __shared__ float scs[32], bss[32];

    const __half* gA = (MODE == 1) ? g_pad1 : g_pad2;
    const __half* gW = (MODE == 1) ? g_wimg1 : g_wimg2;

    int t = threadIdx.x, warp = t >> 5, lane = t & 31;
    int base = 1024 + blockIdx.x * 256;
    int b    = blockIdx.y;
    long volr = (long)b*PADSTR + GUARD;

    if (t < 32) {
        float a = bg[t]*rsqrtf(bv[t] + 1e-5f);
        scs[t] = a;
        bss[t] = (cb[t] - bm[t])*a + bb[t];
    }

    uint32_t Abase = smem_u32(Asm), Bbase = smem_u32(Bsm);
    float acc[2][4][4];
    #pragma unroll
    for (int mt = 0; mt < 2; mt++)
        #pragma unroll
        for (int nb = 0; nb < 4; nb++)
            #pragma unroll
            for (int j = 0; j < 4; j++) acc[mt][nb][j] = 0.f;

    int a_rl = (lane & 7) + ((lane >> 3) & 1)*8;
    int a_cs = lane >> 4;
    int b_rn = (lane & 7) + ((lane >> 4) << 3);
    int b_cs = (lane >> 3) & 1;

    for (int kzy = 0; kzy < 9; kzy++) {
        int kz = kzy/3, ky = kzy - kz*3;
        __syncthreads();
        long rowb = volr + base + (kz - 1)*1156 + (ky - 1)*34 - 1;
        for (int idx = t; idx < 1032; idx += 256) {
            int r = idx >> 2, c = idx & 3;
            float4 v = *reinterpret_cast<const float4*>(gA + (rowb + r)*32 + c*8);
            *reinterpret_cast<float4*>(
                reinterpret_cast<char*>(Asm) + SW64(r*64 + c*16)) = v;
        }
        for (int idx = t; idx < 384; idx += 256) {
            int row = idx >> 2, c = idx & 3;
            int dx = row >> 5, co = row & 31;
            float4 v = *reinterpret_cast<const float4*>(
                gW + ((size_t)(kzy*3 + dx)*32 + co)*32 + c*8);
            *reinterpret_cast<float4*>(
                reinterpret_cast<char*>(Bsm) + dx*2048 + SW64(co*64 + c*16)) = v;
        }
        __syncthreads();
        #pragma unroll
        for (int dx = 0; dx < 3; dx++) {
            #pragma unroll
            for (int ks = 0; ks < 2; ks++) {
                uint32_t a[2][4];
                #pragma unroll
                for (int mt = 0; mt < 2; mt++) {
                    int row = warp*32 + mt*16 + a_rl + dx;
                    ldmx4(a[mt], Abase + SW64(row*64 + (2*ks + a_cs)*16));
                }
                uint32_t bf[8];
                #pragma unroll
                for (int np = 0; np < 2; np++) {
                    int rn = np*16 + b_rn;
                    ldmx4(&bf[np*4],
                          Bbase + dx*2048 + SW64(rn*64 + (2*ks + b_cs)*16));
                }
                #pragma unroll
                for (int mt = 0; mt < 2; mt++)
                    #pragma unroll
                    for (int nb = 0; nb < 4; nb++) {
                        int bi = (nb >> 1)*4 + (nb & 1)*2;
                        mma_fp16(acc[mt][nb], a[mt], bf[bi], bf[bi + 1]);
                    }
            }
        }
    }

    int cl = lane & 3;
    #pragma unroll
    for (int mt = 0; mt < 2; mt++)
        #pragma unroll
        for (int half = 0; half < 2; half++) {
            int m = base + warp*32 + mt*16 + (lane >> 2) + half*8;
            int zp = m / 1156; int rem = m - zp*1156;
            int yp = rem / 34; int xp = rem - yp*34;
            if (zp < 1 || zp > 32 || yp < 1 || yp > 32 || xp < 1 || xp > 32) continue;
            if (MODE == 1) {
                __half* dst = g_pad2 + (volr + m)*32;
                #pragma unroll
                for (int nb = 0; nb < 4; nb++) {
                    int co = nb*8 + 2*cl;
                    float v0 = acc[mt][nb][half*2]    *scs[co]   + bss[co];
                    float v1 = acc[mt][nb][half*2 + 1]*scs[co+1] + bss[co+1];
                    v0 = (v0 > 0.f) ? v0 : 0.01f*v0;
                    v1 = (v1 > 0.f) ? v1 : 0.01f*v1;
                    *reinterpret_cast<__half2*>(dst + co) =
                        __half2(__float2half_rn(v0), __float2half_rn(v1));
                }
            } else {
                int n = (zp - 1)*1024 + (yp - 1)*32 + (xp - 1);
                const float* sk = g_skiptm + ((size_t)b*NN + n)*CC;
                float* dst = g_y2tm + ((size_t)b*NN + n)*CC;
                #pragma unroll
                for (int nb = 0; nb < 4; nb++) {
                    int co = nb*8 + 2*cl;
                    float2 s = *reinterpret_cast<const float2*>(sk + co);
                    float v0 = acc[mt][nb][half*2]    *scs[co]   + bss[co]   + s.x;
                    float v1 = acc[mt][nb][half*2 + 1]*scs[co+1] + bss[co+1] + s.y;
                    v0 = (v0 > 0.f) ? v0 : 0.01f*v0;
                    v1 = (v1 > 0.f) ? v1 : 0.01f*v1;
                    *reinterpret_cast<float2*>(dst + co) = make_float2(v0, v1);
                }
            }
        }
}

// ---------------- final: 1x1 conv residual (reads token-major y2) ----------------
__global__ __launch_bounds__(256) void k_final(
    const float* __restrict__ wp, const float* __restrict__ bp,
    float* __restrict__ outp)
{
    __shared__ float ys[64][33];
    __shared__ float wsm[32][32];
    __shared__ float bsh[32];
    int b  = blockIdx.x >> 9;
    int n0 = (blockIdx.x & 511) << 6;
    int t  = threadIdx.x;
    for (int i = t; i < 2048; i += 256) {
        int nn = i >> 5, ci = i & 31;
        ys[nn][ci] = g_y2tm[((size_t)b*NN + n0 + nn)*CC + ci];
    }
    for (int i = t; i < 1024; i += 256) wsm[i >> 5][i & 31] = wp[i];
    if (t < 32) bsh[t] = bp[t];
    __syncthreads();
    int nn = t & 63;
    int cg = t >> 6;
    #pragma unroll
    for (int cc = 0; cc < 8; cc++) {
        int co = cg*8 + cc;
        float s = bsh[co];
        #pragma unroll
        for (int ci = 0; ci < 32; ci++) s += wsm[co][ci]*ys[nn][ci];
        int idx = (b*32 + co)*NN + n0 + nn;
        outp[idx] = g_skip[idx] + s;
    }
}

// ---------------- launch ----------------
extern "C" void kernel_launch(void* const* d_in, const int* in_sizes, int n_in,
                              void* d_out, int out_size)
{
    const float* x    = (const float*)d_in[0];
    const float* pos  = (const float*)d_in[1];
    const float* lng  = (const float*)d_in[2];
    const float* lnb  = (const float*)d_in[3];
    const float* gam  = (const float*)d_in[4];
    const float* Wq   = (const float*)d_in[5];
    const float* EFw  = (const float*)d_in[6];
    const float* EFb  = (const float*)d_in[7];
    const float* t1   = (const float*)d_in[8];
    const float* t2   = (const float*)d_in[9];
    const float* o1w  = (const float*)d_in[10];
    const float* o1b  = (const float*)d_in[11];
    const float* o2w  = (const float*)d_in[12];
    const float* o2b  = (const float*)d_in[13];
    const float* c1w  = (const float*)d_in[14];
    const float* c1b  = (const float*)d_in[15];
    const float* b1g  = (const float*)d_in[16];
    const float* b1b  = (const float*)d_in[17];
    const float* b1m  = (const float*)d_in[18];
    const float* b1v  = (const float*)d_in[19];
    const float* c2w  = (const float*)d_in[20];
    const float* c2b  = (const float*)d_in[21];
    const float* b2g  = (const float*)d_in[22];
    const float* b2b  = (const float*)d_in[23];
    const float* b2m  = (const float*)d_in[24];
    const float* b2v  = (const float*)d_in[25];
    const float* cpw  = (const float*)d_in[26];
    const float* cpb  = (const float*)d_in[27];
    float* outp = (float*)d_out;

    // launch index 3 = k1 (profiled this round)
    k_ef_prep<<<2048, 256>>>(EFw);                                 // 0
    kw_prep<<<108, 256>>>(c1w, 0);                                 // 1
    kw_prep<<<108, 256>>>(c2w, 1);                                 // 2
    k1_tok_ln_qkvv<<<4096, 256>>>(x, pos, lng, lnb, Wq);          // 3  <- profiled
    k3a_gram_partial<<<dim3(8, 16), 256>>>();                      // 4
    k2_mma<<<dim3(KSPLIT, 2), 256>>>();                            // 5
    k2_proj_reduce<<<64, 256>>>(EFb);                              // 6
    k3a_finalize<<<16, 128>>>(t1);                                 // 7
    k3b_attn<<<dim3(256, 16), 128>>>(t2);                          // 8
    k4_combine<<<4096, 128>>>(o1w, o1b, o2w, o2b, gam);            // 9
    conv_mma<1><<<dim3(NTILE2, BB), 256>>>(c1b, b1g, b1b, b1m, b1v);
    conv_mma<2><<<dim3(NTILE2, BB), 256>>>(c2b, b2g, b2b, b2m, b2v);
    k_final<<<2048, 256>>>(cpw, cpb, outp);
}